// round 10
// baseline (speedup 1.0000x reference)
#include <cuda_runtime.h>
#include <cuda_bf16.h>
#include <cstdint>

// ---------------------------------------------------------------------------
// manyToManyGRU: B=32, T=128, DIN=DOUT=1024, fp32.
//
// R9 vs R8 (2120us):
//   - recurrence k-loops use packed fma.rn.f32x2 (2 FMAs/instr, b64 regs fed
//     straight from ld.shared.v2.u64 / ld.global.cg.v2.u64 -> no pack movs)
//   - hierarchical grid barrier: 16 padded group counters + root (cuts
//     same-address atomic serialization from 128 to 8+16 per barrier)
//   - 4 split launches fused into one float4-vectorized kernel
//   - depth-4 software prefetch of the h/rh broadcast loads
// ---------------------------------------------------------------------------

#define B_   32
#define T_   128
#define D_   1024
#define NCTA 128
#define JPC  8
#define TPB  512
#define NW   16
#define KC   16
#define NGRP 16
#define GRPSZ 8
#define U_SMEM_BYTES (3*JPC*D_*4)   // 96 KB

// gx layout: [(g*T + t)*B + b]*D + j
__device__ __align__(16) float g_gx[(size_t)3*T_*B_*D_];
__device__ __align__(16) float g_hT[D_*B_];     // ((k>>2)*B + b)*4 + (k&3)
__device__ __align__(16) float g_rhT[D_*B_];
__device__ __align__(128) unsigned g_bar_cnt[NGRP*32];  // 128B stride per ctr
__device__ unsigned g_bar_root = 0;
__device__ unsigned g_bar_gen  = 0;

// bf16 split planes
__device__ __align__(16) __nv_bfloat16 g_Wb[2][(size_t)3*D_*D_];  // [(g*1024+j)*1024+k]
__device__ __align__(16) __nv_bfloat16 g_xb[2][(size_t)B_*T_*D_]; // [(b*T+t)*1024+k]

__device__ __forceinline__ float sigm(float v) { return 1.0f / (1.0f + __expf(-v)); }

__device__ __forceinline__ uint32_t smem_to_u32(const void* p) {
    uint32_t a;
    asm("{ .reg .u64 t; cvta.to.shared.u64 t, %1; cvt.u32.u64 %0, t; }"
        : "=r"(a) : "l"(p));
    return a;
}
__device__ __forceinline__ void ldsm4(uint32_t* r, uint32_t a) {
    asm volatile("ldmatrix.sync.aligned.m8n8.x4.shared.b16 {%0,%1,%2,%3}, [%4];"
        : "=r"(r[0]), "=r"(r[1]), "=r"(r[2]), "=r"(r[3]) : "r"(a));
}
__device__ __forceinline__ void ldsm2(uint32_t* r, uint32_t a) {
    asm volatile("ldmatrix.sync.aligned.m8n8.x2.shared.b16 {%0,%1}, [%2];"
        : "=r"(r[0]), "=r"(r[1]) : "r"(a));
}
__device__ __forceinline__ void mma16816(float* c, const uint32_t* a, const uint32_t* b) {
    asm volatile("mma.sync.aligned.m16n8k16.row.col.f32.bf16.bf16.f32 "
        "{%0,%1,%2,%3}, {%4,%5,%6,%7}, {%8,%9}, {%0,%1,%2,%3};"
        : "+f"(c[0]), "+f"(c[1]), "+f"(c[2]), "+f"(c[3])
        : "r"(a[0]), "r"(a[1]), "r"(a[2]), "r"(a[3]), "r"(b[0]), "r"(b[1]));
}
// packed f32x2 FMA (FFMA2): d = a*b + c on both 32-bit halves
__device__ __forceinline__ unsigned long long ffma2(unsigned long long a,
                                                    unsigned long long b,
                                                    unsigned long long c) {
    unsigned long long d;
    asm("fma.rn.f32x2 %0, %1, %2, %3;" : "=l"(d) : "l"(a), "l"(b), "l"(c));
    return d;
}
__device__ __forceinline__ float f2x_sum(unsigned long long v) {
    float lo, hi;
    asm("mov.b64 {%0,%1}, %2;" : "=f"(lo), "=f"(hi) : "l"(v));
    return lo + hi;
}
__device__ __forceinline__ void ldcg_v2u64(const void* p, unsigned long long& a,
                                           unsigned long long& b) {
    asm volatile("ld.global.cg.v2.u64 {%0,%1}, [%2];"
                 : "=l"(a), "=l"(b) : "l"(p));
}

// ===================== kernel 1: fused fp32 -> bf16 (hi,lo) split ==========
__global__ void split_all(const float* __restrict__ Wz, const float* __restrict__ Wr,
                          const float* __restrict__ Wh, const float* __restrict__ x)
{
    const int NW4 = (3*D_*D_) / 4;          // float4s in W planes (786432)
    const int NX4 = (B_*T_*D_) / 4;         // float4s in x plane (1048576)
    const int tot = NW4 + NX4;
    for (int i = blockIdx.x*blockDim.x + threadIdx.x; i < tot;
         i += gridDim.x*blockDim.x) {
        const float4 v = (i < NW4)
            ? ((i < NW4/3) ? __ldg((const float4*)Wz + i)
               : (i < 2*(NW4/3)) ? __ldg((const float4*)Wr + (i - NW4/3))
                                 : __ldg((const float4*)Wh + (i - 2*(NW4/3))))
            : __ldg((const float4*)x + (i - NW4));
        __nv_bfloat16 h0 = __float2bfloat16(v.x), h1 = __float2bfloat16(v.y);
        __nv_bfloat16 h2 = __float2bfloat16(v.z), h3 = __float2bfloat16(v.w);
        __nv_bfloat16 l0 = __float2bfloat16(v.x - __bfloat162float(h0));
        __nv_bfloat16 l1 = __float2bfloat16(v.y - __bfloat162float(h1));
        __nv_bfloat16 l2 = __float2bfloat16(v.z - __bfloat162float(h2));
        __nv_bfloat16 l3 = __float2bfloat16(v.w - __bfloat162float(h3));
        uint2 hp, lp;
        hp.x = ((uint32_t)__bfloat16_as_ushort(h1) << 16) | __bfloat16_as_ushort(h0);
        hp.y = ((uint32_t)__bfloat16_as_ushort(h3) << 16) | __bfloat16_as_ushort(h2);
        lp.x = ((uint32_t)__bfloat16_as_ushort(l1) << 16) | __bfloat16_as_ushort(l0);
        lp.y = ((uint32_t)__bfloat16_as_ushort(l3) << 16) | __bfloat16_as_ushort(l2);
        if (i < NW4) {
            *(uint2*)&g_Wb[0][(size_t)i*4] = hp;
            *(uint2*)&g_Wb[1][(size_t)i*4] = lp;
        } else {
            *(uint2*)&g_xb[0][(size_t)(i - NW4)*4] = hp;
            *(uint2*)&g_xb[1][(size_t)(i - NW4)*4] = lp;
        }
    }
}

// ===================== kernel 2: mma.sync GEMM for gx (as R8) ==============
#define GM_THREADS 256
#define ASTRIDE 40
#define PLANE   (128*ASTRIDE)
#define GEMM_SMEM (4*PLANE*2)

__global__ void __launch_bounds__(GM_THREADS, 2)
gemm_kernel(const float* __restrict__ bz, const float* __restrict__ cz,
            const float* __restrict__ br, const float* __restrict__ cr,
            const float* __restrict__ bh, const float* __restrict__ ch)
{
    extern __shared__ __nv_bfloat16 sm[];
    const int tid  = threadIdx.x;
    const int w    = tid >> 5;
    const int lane = tid & 31;
    const int wm   = w >> 2;
    const int wn   = w & 3;
    const int mbase = blockIdx.y * 128;
    const int nbase = blockIdx.x * 128;
    const uint32_t smb = smem_to_u32(sm);

    float acc[4][4][4];
    #pragma unroll
    for (int mf = 0; mf < 4; mf++)
        #pragma unroll
        for (int nf = 0; nf < 4; nf++)
            #pragma unroll
            for (int i = 0; i < 4; i++) acc[mf][nf][i] = 0.0f;

    for (int kc = 0; kc < 32; kc++) {
        #pragma unroll
        for (int it = 0; it < 8; it++) {
            const int idx  = tid + it * GM_THREADS;
            const int part = idx >> 9;
            const int rem  = idx & 511;
            const int row  = rem >> 2;
            const int chk  = rem & 3;
            const uint4* src = (part < 2)
                ? (const uint4*)&g_Wb[part    ][((size_t)(mbase + row) << 10) + kc*32 + chk*8]
                : (const uint4*)&g_xb[part - 2][((size_t)(nbase + row) << 10) + kc*32 + chk*8];
            *(uint4*)&sm[part*PLANE + row*ASTRIDE + chk*8] = __ldg(src);
        }
        __syncthreads();

        #pragma unroll
        for (int h = 0; h < 2; h++) {
            const int k16 = h * 16;
            uint32_t af[4][4], bhf[4][2], blf[4][2];
            #pragma unroll
            for (int mf = 0; mf < 4; mf++) {
                const uint32_t a = smb + 2u*(0*PLANE +
                    (wm*64 + mf*16 + (lane & 15))*ASTRIDE + k16 + (lane >> 4)*8);
                ldsm4(af[mf], a);
            }
            #pragma unroll
            for (int nf = 0; nf < 4; nf++) {
                const uint32_t rc = (wn*32 + nf*8 + (lane & 7))*ASTRIDE + k16 + ((lane >> 3) & 1)*8;
                ldsm2(bhf[nf], smb + 2u*(2*PLANE + rc));
                ldsm2(blf[nf], smb + 2u*(3*PLANE + rc));
            }
            #pragma unroll
            for (int mf = 0; mf < 4; mf++)
                #pragma unroll
                for (int nf = 0; nf < 4; nf++) {
                    mma16816(acc[mf][nf], af[mf], bhf[nf]);
                    mma16816(acc[mf][nf], af[mf], blf[nf]);
                }
            #pragma unroll
            for (int mf = 0; mf < 4; mf++) {
                const uint32_t a = smb + 2u*(1*PLANE +
                    (wm*64 + mf*16 + (lane & 15))*ASTRIDE + k16 + (lane >> 4)*8);
                ldsm4(af[mf], a);
            }
            #pragma unroll
            for (int mf = 0; mf < 4; mf++)
                #pragma unroll
                for (int nf = 0; nf < 4; nf++)
                    mma16816(acc[mf][nf], af[mf], bhf[nf]);
        }
        __syncthreads();
    }

    const int g = mbase >> 10;
    const float* bp = (g == 0) ? bz : (g == 1) ? br : bh;
    const float* cp = (g == 0) ? cz : (g == 1) ? cr : ch;
    #pragma unroll
    for (int mf = 0; mf < 4; mf++) {
        const int row0 = wm*64 + mf*16 + (lane >> 2);
        const int jl0  = (mbase + row0) & 1023;
        const int jl8  = (mbase + row0 + 8) & 1023;
        const float bias0 = bp[jl0] + cp[jl0];
        const float bias8 = bp[jl8] + cp[jl8];
        #pragma unroll
        for (int nf = 0; nf < 4; nf++) {
            const int col0 = wn*32 + nf*8 + (lane & 3)*2;
            #pragma unroll
            for (int cc = 0; cc < 2; cc++) {
                const int n = nbase + col0 + cc;
                const int b = n >> 7;
                const int t = n & 127;
                const size_t base = ((size_t)(g*T_ + t)*B_ + b)*D_;
                g_gx[base + jl0] = acc[mf][nf][cc]     + bias0;
                g_gx[base + jl8] = acc[mf][nf][cc + 2] + bias8;
            }
        }
    }
}

// ===================== kernel 3: persistent recurrence =====================
__device__ __forceinline__ void grid_barrier(int grp)
{
    __syncthreads();
    if (threadIdx.x == 0) {
        __threadfence();                                   // release our stores
        unsigned gen = *((volatile unsigned*)&g_bar_gen);  // capture BEFORE arrive
        __threadfence();
        if (atomicAdd(&g_bar_cnt[grp*32], 1u) == GRPSZ - 1u) {
            g_bar_cnt[grp*32] = 0u;
            __threadfence();
            if (atomicAdd(&g_bar_root, 1u) == NGRP - 1u) {
                g_bar_root = 0u;
                __threadfence();
                atomicAdd(&g_bar_gen, 1u);
            } else {
                while (*((volatile unsigned*)&g_bar_gen) == gen) { }
            }
        } else {
            while (*((volatile unsigned*)&g_bar_gen) == gen) { }
        }
        __threadfence();                                   // acquire
    }
    __syncthreads();
}

__global__ void __launch_bounds__(TPB, 1)
gru_kernel(const float* __restrict__ Uz, const float* __restrict__ Ur,
           const float* __restrict__ Uh, float* __restrict__ out)
{
    extern __shared__ float smem[];          // [3][JPC][D] U slices (96 KB)
    __shared__ float spar[2][NW*256];
    __shared__ float sh_z[256];
    __shared__ float sh_h[256];

    const int tid  = threadIdx.x;
    const int w    = tid >> 5;
    const int lane = tid & 31;
    const int j0   = blockIdx.x * JPC;
    const int grp  = blockIdx.x >> 3;

    for (int i = tid; i < JPC*D_; i += TPB) {
        int jj = i >> 10, k = i & (D_-1);
        smem[0*JPC*D_ + i] = Uz[(j0+jj)*D_ + k];
        smem[1*JPC*D_ + i] = Ur[(j0+jj)*D_ + k];
        smem[2*JPC*D_ + i] = Uh[(j0+jj)*D_ + k];
    }
    if (tid < JPC*B_) {
        const int k = j0 + (tid >> 5);
        g_hT[(((k>>2)*B_) + (tid & 31))*4 + (k&3)] = 0.0f;
    }
    if (tid < 256) sh_h[tid] = 0.0f;

    grid_barrier(grp);

    const int k4b = w * KC;
    const int b   = lane;
    const float4* h4  = (const float4*)g_hT;
    const float4* rh4 = (const float4*)g_rhT;

    const int rg  = tid >> 8;          // 0=z-gate, 1=r-gate
    const int ri  = tid & 255;
    const int rjj = ri & 7;
    const int rbb = ri >> 3;
    const int rj  = j0 + rjj;

    for (int t = 0; t < T_; t++) {
        const float gxA = g_gx[((size_t)(rg*T_ + t)*B_ + rbb)*D_ + rj];
        const float gxB = g_gx[((size_t)(2 *T_ + t)*B_ + rbb)*D_ + rj];

        // ===== phase A: z, r (packed f32x2 FMA, depth-4 h prefetch) =====
        unsigned long long az2[JPC], ar2[JPC];
        #pragma unroll
        for (int jj = 0; jj < JPC; jj++) { az2[jj] = 0ull; ar2[jj] = 0ull; }

        unsigned long long hx[4], hz[4];
        #pragma unroll
        for (int u = 0; u < 4; u++)
            ldcg_v2u64(&h4[(k4b+u)*B_ + b], hx[u], hz[u]);

        #pragma unroll
        for (int kk = 0; kk < KC; kk++) {
            const unsigned long long cxy = hx[kk & 3], czw = hz[kk & 3];
            if (kk + 4 < KC)
                ldcg_v2u64(&h4[(k4b+kk+4)*B_ + b], hx[kk & 3], hz[kk & 3]);
            #pragma unroll
            for (int jj = 0; jj < JPC; jj++) {
                const ulonglong2 wz = *(const ulonglong2*)&smem[(0*JPC+jj)*D_ + ((k4b+kk)<<2)];
                const ulonglong2 wr = *(const ulonglong2*)&smem[(1*JPC+jj)*D_ + ((k4b+kk)<<2)];
                az2[jj] = ffma2(cxy, wz.x, az2[jj]);
                az2[jj] = ffma2(czw, wz.y, az2[jj]);
                ar2[jj] = ffma2(cxy, wr.x, ar2[jj]);
                ar2[jj] = ffma2(czw, wr.y, ar2[jj]);
            }
        }
        {
            float4* pz = (float4*)&spar[0][w*256 + b*8];
            float4* pr = (float4*)&spar[1][w*256 + b*8];
            pz[0] = make_float4(f2x_sum(az2[0]), f2x_sum(az2[1]),
                                f2x_sum(az2[2]), f2x_sum(az2[3]));
            pz[1] = make_float4(f2x_sum(az2[4]), f2x_sum(az2[5]),
                                f2x_sum(az2[6]), f2x_sum(az2[7]));
            pr[0] = make_float4(f2x_sum(ar2[0]), f2x_sum(ar2[1]),
                                f2x_sum(ar2[2]), f2x_sum(ar2[3]));
            pr[1] = make_float4(f2x_sum(ar2[4]), f2x_sum(ar2[5]),
                                f2x_sum(ar2[6]), f2x_sum(ar2[7]));
        }
        __syncthreads();
        {
            float s = gxA;
            #pragma unroll
            for (int w2 = 0; w2 < NW; w2++) s += spar[rg][w2*256 + ri];
            const float v = sigm(s);
            if (rg == 0) sh_z[ri] = v;
            else         g_rhT[((rj>>2)*B_ + rbb)*4 + (rj&3)] = v * sh_h[ri];
        }
        grid_barrier(grp);

        // ===== phase B: candidate + update =====
        unsigned long long ah2[JPC];
        #pragma unroll
        for (int jj = 0; jj < JPC; jj++) ah2[jj] = 0ull;

        #pragma unroll
        for (int u = 0; u < 4; u++)
            ldcg_v2u64(&rh4[(k4b+u)*B_ + b], hx[u], hz[u]);

        #pragma unroll
        for (int kk = 0; kk < KC; kk++) {
            const unsigned long long cxy = hx[kk & 3], czw = hz[kk & 3];
            if (kk + 4 < KC)
                ldcg_v2u64(&rh4[(k4b+kk+4)*B_ + b], hx[kk & 3], hz[kk & 3]);
            #pragma unroll
            for (int jj = 0; jj < JPC; jj++) {
                const ulonglong2 wh = *(const ulonglong2*)&smem[(2*JPC+jj)*D_ + ((k4b+kk)<<2)];
                ah2[jj] = ffma2(cxy, wh.x, ah2[jj]);
                ah2[jj] = ffma2(czw, wh.y, ah2[jj]);
            }
        }
        {
            float4* ph = (float4*)&spar[0][w*256 + b*8];
            ph[0] = make_float4(f2x_sum(ah2[0]), f2x_sum(ah2[1]),
                                f2x_sum(ah2[2]), f2x_sum(ah2[3]));
            ph[1] = make_float4(f2x_sum(ah2[4]), f2x_sum(ah2[5]),
                                f2x_sum(ah2[6]), f2x_sum(ah2[7]));
        }
        __syncthreads();
        if (tid < 256) {
            float s = gxB;
            #pragma unroll
            for (int w2 = 0; w2 < NW; w2++) s += spar[0][w2*256 + tid];
            const float hh   = sigm(s);
            const float hold = sh_h[tid];
            const float hn   = fmaf(sh_z[tid], hh - hold, hold);
            // reference reshape: flat output memory layout is (T,B,D)
            out[(size_t)t*(B_*D_) + rbb*D_ + rj] = hn;
            g_hT[((rj>>2)*B_ + rbb)*4 + (rj&3)] = hn;
            sh_h[tid] = hn;
        }
        grid_barrier(grp);
    }
}

// ===================== launch =====================
extern "C" void kernel_launch(void* const* d_in, const int* in_sizes, int n_in,
                              void* d_out, int out_size)
{
    (void)in_sizes; (void)n_in; (void)out_size;
    const float* x  = (const float*)d_in[0];
    const float* Wz = (const float*)d_in[1];
    const float* bz = (const float*)d_in[2];
    const float* Uz = (const float*)d_in[3];
    const float* cz = (const float*)d_in[4];
    const float* Wr = (const float*)d_in[5];
    const float* br = (const float*)d_in[6];
    const float* Ur = (const float*)d_in[7];
    const float* cr = (const float*)d_in[8];
    const float* Wh = (const float*)d_in[9];
    const float* bh = (const float*)d_in[10];
    const float* Uh = (const float*)d_in[11];
    const float* ch = (const float*)d_in[12];
    float* out = (float*)d_out;

    // 1) fused bf16 hi/lo split
    split_all<<<2048, 256>>>(Wz, Wr, Wh, x);

    // 2) mma.sync GEMM -> g_gx (+bias)
    cudaFuncSetAttribute(gemm_kernel, cudaFuncAttributeMaxDynamicSharedMemorySize,
                         GEMM_SMEM);
    gemm_kernel<<<dim3(32, 24), GM_THREADS, GEMM_SMEM>>>(bz, cz, br, cr, bh, ch);

    // 3) persistent recurrence
    cudaFuncSetAttribute(gru_kernel, cudaFuncAttributeMaxDynamicSharedMemorySize,
                         U_SMEM_BYTES);
    gru_kernel<<<NCTA, TPB, U_SMEM_BYTES>>>(Uz, Ur, Uh, out);
}

// round 11
// speedup vs baseline: 1.4253x; 1.4253x over previous
#include <cuda_runtime.h>
#include <cuda_bf16.h>
#include <cstdint>

// ---------------------------------------------------------------------------
// manyToManyGRU: B=32, T=128, DIN=DOUT=1024, fp32.
//
// R10 vs R9 (2172us, neutral): recurrence GEMMs moved onto mma.sync bf16
// (hi/lo split) as well. U weights pre-split to bf16 planes and preloaded as
// per-warp B-fragments in REGISTERS (no smem weights, no broadcast LDS).
// h / rh are broadcast between CTAs in an mma-fragment-linear bf16 hi/lo
// layout: producers (reduction threads) scatter 2x2 u16 per value; consumers
// load A-fragments with coalesced ld.global.cg.v4.u32. h itself stays fp32
// in per-CTA smem (sh_h), so only gate pre-activations see bf16-split error.
//   kernel 1: split W,U,x -> bf16 hi/lo planes
//   kernel 2: mma.sync GEMM gx = W·x^T (+bias), layout [g][t][b][j]  (as R8)
//   kernel 3: persistent recurrence, mma.sync per phase, 2 grid barriers/step
// ---------------------------------------------------------------------------

#define B_   32
#define T_   128
#define D_   1024
#define NCTA 128
#define JPC  8
#define TPB  512
#define NW   16
#define NGRP 16
#define GRPSZ 8

// gx layout: [(g*T + t)*B + b]*D + j
__device__ __align__(16) float g_gx[(size_t)3*T_*B_*D_];
// h / rh broadcast planes, fragment-linear (see hfrag_off): [plane][b32 idx]
__device__ __align__(16) uint32_t g_hA[2][NW*1024];
__device__ __align__(16) uint32_t g_rA[2][NW*1024];
__device__ __align__(128) unsigned g_bar_cnt[NGRP*32];
__device__ unsigned g_bar_root = 0;
__device__ unsigned g_bar_gen  = 0;

// bf16 split planes
__device__ __align__(16) __nv_bfloat16 g_Wb[2][(size_t)3*D_*D_];  // [(g*1024+j)*1024+k]
__device__ __align__(16) __nv_bfloat16 g_Ub[2][(size_t)3*D_*D_];  // [(g*1024+j)*1024+k]
__device__ __align__(16) __nv_bfloat16 g_xb[2][(size_t)B_*T_*D_]; // [(b*T+t)*1024+k]

__device__ __forceinline__ float sigm(float v) { return 1.0f / (1.0f + __expf(-v)); }

__device__ __forceinline__ uint32_t smem_to_u32(const void* p) {
    uint32_t a;
    asm("{ .reg .u64 t; cvta.to.shared.u64 t, %1; cvt.u32.u64 %0, t; }"
        : "=r"(a) : "l"(p));
    return a;
}
__device__ __forceinline__ void ldsm4(uint32_t* r, uint32_t a) {
    asm volatile("ldmatrix.sync.aligned.m8n8.x4.shared.b16 {%0,%1,%2,%3}, [%4];"
        : "=r"(r[0]), "=r"(r[1]), "=r"(r[2]), "=r"(r[3]) : "r"(a));
}
__device__ __forceinline__ void ldsm2(uint32_t* r, uint32_t a) {
    asm volatile("ldmatrix.sync.aligned.m8n8.x2.shared.b16 {%0,%1}, [%2];"
        : "=r"(r[0]), "=r"(r[1]) : "r"(a));
}
__device__ __forceinline__ void mma16816(float* c, const uint32_t* a, const uint32_t* b) {
    asm volatile("mma.sync.aligned.m16n8k16.row.col.f32.bf16.bf16.f32 "
        "{%0,%1,%2,%3}, {%4,%5,%6,%7}, {%8,%9}, {%0,%1,%2,%3};"
        : "+f"(c[0]), "+f"(c[1]), "+f"(c[2]), "+f"(c[3])
        : "r"(a[0]), "r"(a[1]), "r"(a[2]), "r"(a[3]), "r"(b[0]), "r"(b[1]));
}

// fragment-linear b32 index of value (b, k) inside the h/rh planes.
// Consumer warp w = k>>6 reads frag (kt*2+mt) as 4 consecutive b32 per lane:
//   base = w*1024 + (kt*2+mt)*128 + lane*4 + reg ; u16 half = k&1.
__device__ __forceinline__ uint32_t hfrag_off(int b, int k) {
    const int w  = k >> 6;
    const int kl = k & 63;
    const int kt = kl >> 4;
    const int kin = kl & 15;
    const int mt = b >> 4;
    const int rr = b & 15;
    const int lane = (rr & 7)*4 + ((kin & 7) >> 1);
    const int reg  = (rr >> 3) | ((kin >> 3) << 1);
    return (uint32_t)(w*1024 + ((kt*2 + mt)*32 + lane)*4 + reg);
}

// ===================== kernel 1: fused fp32 -> bf16 (hi,lo) split ==========
__global__ void split_all(const float* __restrict__ Wz, const float* __restrict__ Wr,
                          const float* __restrict__ Wh, const float* __restrict__ Uz,
                          const float* __restrict__ Ur, const float* __restrict__ Uh,
                          const float* __restrict__ x)
{
    const int M4  = (D_*D_) / 4;            // 262144 float4 per matrix
    const int NX4 = (B_*T_*D_) / 4;         // 1048576
    const int tot = 6*M4 + NX4;
    for (int i = blockIdx.x*blockDim.x + threadIdx.x; i < tot;
         i += gridDim.x*blockDim.x) {
        float4 v;
        int mat, off;
        if (i < 6*M4) {
            mat = i / M4; off = i - mat*M4;
            const float* src = (mat==0)?Wz:(mat==1)?Wr:(mat==2)?Wh:
                               (mat==3)?Uz:(mat==4)?Ur:Uh;
            v = __ldg((const float4*)src + off);
        } else {
            mat = 7; off = i - 6*M4;
            v = __ldg((const float4*)x + off);
        }
        __nv_bfloat16 h0 = __float2bfloat16(v.x), h1 = __float2bfloat16(v.y);
        __nv_bfloat16 h2 = __float2bfloat16(v.z), h3 = __float2bfloat16(v.w);
        __nv_bfloat16 l0 = __float2bfloat16(v.x - __bfloat162float(h0));
        __nv_bfloat16 l1 = __float2bfloat16(v.y - __bfloat162float(h1));
        __nv_bfloat16 l2 = __float2bfloat16(v.z - __bfloat162float(h2));
        __nv_bfloat16 l3 = __float2bfloat16(v.w - __bfloat162float(h3));
        uint2 hp, lp;
        hp.x = ((uint32_t)__bfloat16_as_ushort(h1) << 16) | __bfloat16_as_ushort(h0);
        hp.y = ((uint32_t)__bfloat16_as_ushort(h3) << 16) | __bfloat16_as_ushort(h2);
        lp.x = ((uint32_t)__bfloat16_as_ushort(l1) << 16) | __bfloat16_as_ushort(l0);
        lp.y = ((uint32_t)__bfloat16_as_ushort(l3) << 16) | __bfloat16_as_ushort(l2);
        if (mat < 3) {
            *(uint2*)&g_Wb[0][(size_t)mat*D_*D_ + (size_t)off*4] = hp;
            *(uint2*)&g_Wb[1][(size_t)mat*D_*D_ + (size_t)off*4] = lp;
        } else if (mat < 6) {
            *(uint2*)&g_Ub[0][(size_t)(mat-3)*D_*D_ + (size_t)off*4] = hp;
            *(uint2*)&g_Ub[1][(size_t)(mat-3)*D_*D_ + (size_t)off*4] = lp;
        } else {
            *(uint2*)&g_xb[0][(size_t)off*4] = hp;
            *(uint2*)&g_xb[1][(size_t)off*4] = lp;
        }
    }
}

// ===================== kernel 2: mma.sync GEMM for gx (as R8) ==============
#define GM_THREADS 256
#define ASTRIDE 40
#define PLANE   (128*ASTRIDE)
#define GEMM_SMEM (4*PLANE*2)

__global__ void __launch_bounds__(GM_THREADS, 2)
gemm_kernel(const float* __restrict__ bz, const float* __restrict__ cz,
            const float* __restrict__ br, const float* __restrict__ cr,
            const float* __restrict__ bh, const float* __restrict__ ch)
{
    extern __shared__ __nv_bfloat16 sm[];
    const int tid  = threadIdx.x;
    const int w    = tid >> 5;
    const int lane = tid & 31;
    const int wm   = w >> 2;
    const int wn   = w & 3;
    const int mbase = blockIdx.y * 128;
    const int nbase = blockIdx.x * 128;
    const uint32_t smb = smem_to_u32(sm);

    float acc[4][4][4];
    #pragma unroll
    for (int mf = 0; mf < 4; mf++)
        #pragma unroll
        for (int nf = 0; nf < 4; nf++)
            #pragma unroll
            for (int i = 0; i < 4; i++) acc[mf][nf][i] = 0.0f;

    for (int kc = 0; kc < 32; kc++) {
        #pragma unroll
        for (int it = 0; it < 8; it++) {
            const int idx  = tid + it * GM_THREADS;
            const int part = idx >> 9;
            const int rem  = idx & 511;
            const int row  = rem >> 2;
            const int chk  = rem & 3;
            const uint4* src = (part < 2)
                ? (const uint4*)&g_Wb[part    ][((size_t)(mbase + row) << 10) + kc*32 + chk*8]
                : (const uint4*)&g_xb[part - 2][((size_t)(nbase + row) << 10) + kc*32 + chk*8];
            *(uint4*)&sm[part*PLANE + row*ASTRIDE + chk*8] = __ldg(src);
        }
        __syncthreads();

        #pragma unroll
        for (int h = 0; h < 2; h++) {
            const int k16 = h * 16;
            uint32_t af[4][4], bhf[4][2], blf[4][2];
            #pragma unroll
            for (int mf = 0; mf < 4; mf++) {
                const uint32_t a = smb + 2u*(0*PLANE +
                    (wm*64 + mf*16 + (lane & 15))*ASTRIDE + k16 + (lane >> 4)*8);
                ldsm4(af[mf], a);
            }
            #pragma unroll
            for (int nf = 0; nf < 4; nf++) {
                const uint32_t rc = (wn*32 + nf*8 + (lane & 7))*ASTRIDE + k16 + ((lane >> 3) & 1)*8;
                ldsm2(bhf[nf], smb + 2u*(2*PLANE + rc));
                ldsm2(blf[nf], smb + 2u*(3*PLANE + rc));
            }
            #pragma unroll
            for (int mf = 0; mf < 4; mf++)
                #pragma unroll
                for (int nf = 0; nf < 4; nf++) {
                    mma16816(acc[mf][nf], af[mf], bhf[nf]);
                    mma16816(acc[mf][nf], af[mf], blf[nf]);
                }
            #pragma unroll
            for (int mf = 0; mf < 4; mf++) {
                const uint32_t a = smb + 2u*(1*PLANE +
                    (wm*64 + mf*16 + (lane & 15))*ASTRIDE + k16 + (lane >> 4)*8);
                ldsm4(af[mf], a);
            }
            #pragma unroll
            for (int mf = 0; mf < 4; mf++)
                #pragma unroll
                for (int nf = 0; nf < 4; nf++)
                    mma16816(acc[mf][nf], af[mf], bhf[nf]);
        }
        __syncthreads();
    }

    const int g = mbase >> 10;
    const float* bp = (g == 0) ? bz : (g == 1) ? br : bh;
    const float* cp = (g == 0) ? cz : (g == 1) ? cr : ch;
    #pragma unroll
    for (int mf = 0; mf < 4; mf++) {
        const int row0 = wm*64 + mf*16 + (lane >> 2);
        const int jl0  = (mbase + row0) & 1023;
        const int jl8  = (mbase + row0 + 8) & 1023;
        const float bias0 = bp[jl0] + cp[jl0];
        const float bias8 = bp[jl8] + cp[jl8];
        #pragma unroll
        for (int nf = 0; nf < 4; nf++) {
            const int col0 = wn*32 + nf*8 + (lane & 3)*2;
            #pragma unroll
            for (int cc = 0; cc < 2; cc++) {
                const int n = nbase + col0 + cc;
                const int b = n >> 7;
                const int t = n & 127;
                const size_t base = ((size_t)(g*T_ + t)*B_ + b)*D_;
                g_gx[base + jl0] = acc[mf][nf][cc]     + bias0;
                g_gx[base + jl8] = acc[mf][nf][cc + 2] + bias8;
            }
        }
    }
}

// ===================== kernel 3: persistent recurrence (mma) ===============
__device__ __forceinline__ void grid_barrier(int grp)
{
    __syncthreads();
    if (threadIdx.x == 0) {
        __threadfence();
        unsigned gen = *((volatile unsigned*)&g_bar_gen);
        __threadfence();
        if (atomicAdd(&g_bar_cnt[grp*32], 1u) == GRPSZ - 1u) {
            g_bar_cnt[grp*32] = 0u;
            __threadfence();
            if (atomicAdd(&g_bar_root, 1u) == NGRP - 1u) {
                g_bar_root = 0u;
                __threadfence();
                atomicAdd(&g_bar_gen, 1u);
            } else {
                while (*((volatile unsigned*)&g_bar_gen) == gen) { }
            }
        } else {
            while (*((volatile unsigned*)&g_bar_gen) == gen) { }
        }
        __threadfence();
    }
    __syncthreads();
}

__global__ void __launch_bounds__(TPB, 1)
gru_kernel(float* __restrict__ out)
{
    __shared__ float spar[2][NW*256];   // partials [gate][w*256 + b*8 + jj]
    __shared__ float sh_z[256];
    __shared__ float sh_h[256];         // canonical fp32 h for this CTA's slice

    const int tid  = threadIdx.x;
    const int w    = tid >> 5;
    const int lane = tid & 31;
    const int j0   = blockIdx.x * JPC;
    const int grp  = blockIdx.x >> 3;
    const int gid  = lane >> 2;
    const int tig  = lane & 3;

    // ---- preload U B-fragments into registers: [gate][plane][ktile][reg]
    uint32_t bu[3][2][4][2];
    {
        const int jrow = j0 + gid;
        const int kb0  = (w << 6) + (tig << 1);
        #pragma unroll
        for (int g = 0; g < 3; g++) {
            const size_t ro = (((size_t)g << 10) + jrow) << 10;
            #pragma unroll
            for (int p = 0; p < 2; p++)
                #pragma unroll
                for (int kt = 0; kt < 4; kt++) {
                    bu[g][p][kt][0] = *(const uint32_t*)&g_Ub[p][ro + kb0 + (kt<<4)];
                    bu[g][p][kt][1] = *(const uint32_t*)&g_Ub[p][ro + kb0 + (kt<<4) + 8];
                }
        }
    }

    // ---- reduction-thread identity + precomputed h/rh scatter pointers
    const int rg  = tid >> 8;          // 0 = z-gate, 1 = r-gate
    const int ri  = tid & 255;
    const int rjj = ri & 7;
    const int rbb = ri >> 3;
    const int rj  = j0 + rjj;
    const uint32_t hoff = hfrag_off(rbb, rj);
    const int      half = rj & 1;
    uint16_t* h0p = (uint16_t*)g_hA[0] + (size_t)hoff*2 + half;
    uint16_t* h1p = (uint16_t*)g_hA[1] + (size_t)hoff*2 + half;
    uint16_t* r0p = (uint16_t*)g_rA[0] + (size_t)hoff*2 + half;
    uint16_t* r1p = (uint16_t*)g_rA[1] + (size_t)hoff*2 + half;

    // ---- init h = 0 (planes + local fp32)
    if (tid < 256) { *h0p = 0; *h1p = 0; sh_h[tid] = 0.0f; }
    grid_barrier(grp);

    const uint32_t abase = (w << 10) + (lane << 2);   // b32 index of lane's frag run

    for (int t = 0; t < T_; t++) {
        const float gxA = g_gx[((size_t)(rg*T_ + t)*B_ + rbb)*D_ + rj];
        const float gxB = g_gx[((size_t)(2 *T_ + t)*B_ + rbb)*D_ + rj];

        // ================= phase A: z, r =================
        float cz[2][4], cr[2][4];
        #pragma unroll
        for (int mt = 0; mt < 2; mt++)
            #pragma unroll
            for (int i = 0; i < 4; i++) { cz[mt][i] = 0.0f; cr[mt][i] = 0.0f; }

        {
            uint4 af[8];
            #pragma unroll
            for (int i = 0; i < 8; i++)                       // h-hi plane
                af[i] = __ldcg((const uint4*)(g_hA[0] + abase + (i << 7)));
            #pragma unroll
            for (int kt = 0; kt < 4; kt++)
                #pragma unroll
                for (int mt = 0; mt < 2; mt++) {
                    const uint32_t* a = (const uint32_t*)&af[kt*2 + mt];
                    mma16816(cz[mt], a, bu[0][0][kt]);        // hh * Uz_hi
                    mma16816(cz[mt], a, bu[0][1][kt]);        // hh * Uz_lo
                    mma16816(cr[mt], a, bu[1][0][kt]);
                    mma16816(cr[mt], a, bu[1][1][kt]);
                }
            #pragma unroll
            for (int i = 0; i < 8; i++)                       // h-lo plane
                af[i] = __ldcg((const uint4*)(g_hA[1] + abase + (i << 7)));
            #pragma unroll
            for (int kt = 0; kt < 4; kt++)
                #pragma unroll
                for (int mt = 0; mt < 2; mt++) {
                    const uint32_t* a = (const uint32_t*)&af[kt*2 + mt];
                    mma16816(cz[mt], a, bu[0][0][kt]);        // hl * Uz_hi
                    mma16816(cr[mt], a, bu[1][0][kt]);
                }
        }
        #pragma unroll
        for (int mt = 0; mt < 2; mt++) {
            const int i0 = w*256 + (mt*16 + gid)*8 + tig*2;
            const int i8 = w*256 + (mt*16 + gid + 8)*8 + tig*2;
            *(float2*)&spar[0][i0] = make_float2(cz[mt][0], cz[mt][1]);
            *(float2*)&spar[0][i8] = make_float2(cz[mt][2], cz[mt][3]);
            *(float2*)&spar[1][i0] = make_float2(cr[mt][0], cr[mt][1]);
            *(float2*)&spar[1][i8] = make_float2(cr[mt][2], cr[mt][3]);
        }
        __syncthreads();
        {
            float s = gxA;
            #pragma unroll
            for (int w2 = 0; w2 < NW; w2++) s += spar[rg][w2*256 + ri];
            const float v = sigm(s);
            if (rg == 0) sh_z[ri] = v;
            else {
                const float rh = v * sh_h[ri];
                const __nv_bfloat16 hi = __float2bfloat16(rh);
                const __nv_bfloat16 lo = __float2bfloat16(rh - __bfloat162float(hi));
                *r0p = __bfloat16_as_ushort(hi);
                *r1p = __bfloat16_as_ushort(lo);
            }
        }
        grid_barrier(grp);

        // ================= phase B: candidate + update =================
        float ch[2][4];
        #pragma unroll
        for (int mt = 0; mt < 2; mt++)
            #pragma unroll
            for (int i = 0; i < 4; i++) ch[mt][i] = 0.0f;

        {
            uint4 af[8];
            #pragma unroll
            for (int i = 0; i < 8; i++)                       // rh-hi plane
                af[i] = __ldcg((const uint4*)(g_rA[0] + abase + (i << 7)));
            #pragma unroll
            for (int kt = 0; kt < 4; kt++)
                #pragma unroll
                for (int mt = 0; mt < 2; mt++) {
                    const uint32_t* a = (const uint32_t*)&af[kt*2 + mt];
                    mma16816(ch[mt], a, bu[2][0][kt]);
                    mma16816(ch[mt], a, bu[2][1][kt]);
                }
            #pragma unroll
            for (int i = 0; i < 8; i++)                       // rh-lo plane
                af[i] = __ldcg((const uint4*)(g_rA[1] + abase + (i << 7)));
            #pragma unroll
            for (int kt = 0; kt < 4; kt++)
                #pragma unroll
                for (int mt = 0; mt < 2; mt++) {
                    const uint32_t* a = (const uint32_t*)&af[kt*2 + mt];
                    mma16816(ch[mt], a, bu[2][0][kt]);
                }
        }
        #pragma unroll
        for (int mt = 0; mt < 2; mt++) {
            const int i0 = w*256 + (mt*16 + gid)*8 + tig*2;
            const int i8 = w*256 + (mt*16 + gid + 8)*8 + tig*2;
            *(float2*)&spar[0][i0] = make_float2(ch[mt][0], ch[mt][1]);
            *(float2*)&spar[0][i8] = make_float2(ch[mt][2], ch[mt][3]);
        }
        __syncthreads();
        if (tid < 256) {
            float s = gxB;
            #pragma unroll
            for (int w2 = 0; w2 < NW; w2++) s += spar[0][w2*256 + tid];
            const float hh   = sigm(s);
            const float hold = sh_h[tid];
            const float hn   = fmaf(sh_z[tid], hh - hold, hold);
            // reference reshape: flat output memory layout is (T,B,D)
            out[(size_t)t*(B_*D_) + rbb*D_ + rj] = hn;
            const __nv_bfloat16 hi = __float2bfloat16(hn);
            const __nv_bfloat16 lo = __float2bfloat16(hn - __bfloat162float(hi));
            *h0p = __bfloat16_as_ushort(hi);
            *h1p = __bfloat16_as_ushort(lo);
            sh_h[tid] = hn;
        }
        grid_barrier(grp);
    }
}

// ===================== launch =====================
extern "C" void kernel_launch(void* const* d_in, const int* in_sizes, int n_in,
                              void* d_out, int out_size)
{
    (void)in_sizes; (void)n_in; (void)out_size;
    const float* x  = (const float*)d_in[0];
    const float* Wz = (const float*)d_in[1];
    const float* bz = (const float*)d_in[2];
    const float* Uz = (const float*)d_in[3];
    const float* cz = (const float*)d_in[4];
    const float* Wr = (const float*)d_in[5];
    const float* br = (const float*)d_in[6];
    const float* Ur = (const float*)d_in[7];
    const float* cr = (const float*)d_in[8];
    const float* Wh = (const float*)d_in[9];
    const float* bh = (const float*)d_in[10];
    const float* Uh = (const float*)d_in[11];
    const float* ch = (const float*)d_in[12];
    float* out = (float*)d_out;

    // 1) fused bf16 hi/lo split (W, U, x)
    split_all<<<2048, 256>>>(Wz, Wr, Wh, Uz, Ur, Uh, x);

    // 2) mma.sync GEMM -> g_gx (+bias)
    cudaFuncSetAttribute(gemm_kernel, cudaFuncAttributeMaxDynamicSharedMemorySize,
                         GEMM_SMEM);
    gemm_kernel<<<dim3(32, 24), GM_THREADS, GEMM_SMEM>>>(bz, cz, br, cr, bh, ch);

    // 3) persistent recurrence (mma.sync, weights in registers)
    gru_kernel<<<NCTA, TPB>>>(out);
}

// round 12
// speedup vs baseline: 1.4548x; 1.0207x over previous
#include <cuda_runtime.h>
#include <cuda_bf16.h>
#include <cstdint>

// ---------------------------------------------------------------------------
// manyToManyGRU: B=32, T=128, DIN=DOUT=1024, fp32.
//
// R11 vs R10 (1524us): recurrence was sync + broadcast-bandwidth bound.
//   - 64 CTAs x JPC=16 (was 128 x 8): halves h/rh all-to-all L2 traffic AND
//     halves grid-barrier fan-in. Same 16-warp fragment pipeline, n=16 via
//     two n8 B-fragments, m-tile-split loop to stay within 128 regs.
//   - grid barrier rebuilt on atom.add.acq_rel.gpu + ld.acquire.gpu (no
//     __threadfence full-membar drains on the critical path).
//   - z/r gates use single-plane (hi) U weights; h-gate keeps U hi+lo and
//     rh hi+lo (state precision preserved; predicted rel_err ~1e-4 << 1e-3).
// ---------------------------------------------------------------------------

#define B_   32
#define T_   128
#define D_   1024
#define NCTA 64
#define JPC  16
#define TPB  512
#define NW   16
#define NGRP 8
#define GRPSZ 8

// gx layout: [(g*T + t)*B + b]*D + j
__device__ __align__(16) float g_gx[(size_t)3*T_*B_*D_];
// h / rh broadcast planes, fragment-linear (see hfrag_off): [plane][b32 idx]
__device__ __align__(16) uint32_t g_hA[2][NW*1024];
__device__ __align__(16) uint32_t g_rA[2][NW*1024];
__device__ __align__(128) unsigned g_bar_cnt[NGRP*32];
__device__ unsigned g_bar_root = 0;
__device__ unsigned g_bar_gen  = 0;

// bf16 split planes
__device__ __align__(16) __nv_bfloat16 g_Wb[2][(size_t)3*D_*D_];  // [(g*1024+j)*1024+k]
__device__ __align__(16) __nv_bfloat16 g_Ub[2][(size_t)3*D_*D_];  // [(g*1024+j)*1024+k]
__device__ __align__(16) __nv_bfloat16 g_xb[2][(size_t)B_*T_*D_]; // [(b*T+t)*1024+k]

__device__ __forceinline__ float sigm(float v) { return 1.0f / (1.0f + __expf(-v)); }

__device__ __forceinline__ uint32_t smem_to_u32(const void* p) {
    uint32_t a;
    asm("{ .reg .u64 t; cvta.to.shared.u64 t, %1; cvt.u32.u64 %0, t; }"
        : "=r"(a) : "l"(p));
    return a;
}
__device__ __forceinline__ void ldsm4(uint32_t* r, uint32_t a) {
    asm volatile("ldmatrix.sync.aligned.m8n8.x4.shared.b16 {%0,%1,%2,%3}, [%4];"
        : "=r"(r[0]), "=r"(r[1]), "=r"(r[2]), "=r"(r[3]) : "r"(a));
}
__device__ __forceinline__ void ldsm2(uint32_t* r, uint32_t a) {
    asm volatile("ldmatrix.sync.aligned.m8n8.x2.shared.b16 {%0,%1}, [%2];"
        : "=r"(r[0]), "=r"(r[1]) : "r"(a));
}
__device__ __forceinline__ void mma16816(float* c, const uint32_t* a, const uint32_t* b) {
    asm volatile("mma.sync.aligned.m16n8k16.row.col.f32.bf16.bf16.f32 "
        "{%0,%1,%2,%3}, {%4,%5,%6,%7}, {%8,%9}, {%0,%1,%2,%3};"
        : "+f"(c[0]), "+f"(c[1]), "+f"(c[2]), "+f"(c[3])
        : "r"(a[0]), "r"(a[1]), "r"(a[2]), "r"(a[3]), "r"(b[0]), "r"(b[1]));
}

// release/acquire barrier primitives (gpu scope)
__device__ __forceinline__ unsigned ld_acq(unsigned* p) {
    unsigned v;
    asm volatile("ld.acquire.gpu.global.u32 %0, [%1];" : "=r"(v) : "l"(p) : "memory");
    return v;
}
__device__ __forceinline__ unsigned atom_inc_acqrel(unsigned* p) {
    unsigned o;
    asm volatile("atom.acq_rel.gpu.global.add.u32 %0, [%1], 1;" : "=r"(o) : "l"(p) : "memory");
    return o;
}
__device__ __forceinline__ void st_rlx(unsigned* p, unsigned v) {
    asm volatile("st.relaxed.gpu.global.u32 [%0], %1;" :: "l"(p), "r"(v) : "memory");
}

// fragment-linear b32 index of value (b, k) inside the h/rh planes.
// Consumer warp w = k>>6 reads frag (kt*2+mt) as 4 consecutive b32 per lane:
//   base = w*1024 + (kt*2+mt)*128 + lane*4 + reg ; u16 half = k&1.
__device__ __forceinline__ uint32_t hfrag_off(int b, int k) {
    const int w  = k >> 6;
    const int kl = k & 63;
    const int kt = kl >> 4;
    const int kin = kl & 15;
    const int mt = b >> 4;
    const int rr = b & 15;
    const int lane = (rr & 7)*4 + ((kin & 7) >> 1);
    const int reg  = (rr >> 3) | ((kin >> 3) << 1);
    return (uint32_t)(w*1024 + ((kt*2 + mt)*32 + lane)*4 + reg);
}

// ===================== kernel 1: fused fp32 -> bf16 (hi,lo) split ==========
__global__ void split_all(const float* __restrict__ Wz, const float* __restrict__ Wr,
                          const float* __restrict__ Wh, const float* __restrict__ Uz,
                          const float* __restrict__ Ur, const float* __restrict__ Uh,
                          const float* __restrict__ x)
{
    const int M4  = (D_*D_) / 4;
    const int NX4 = (B_*T_*D_) / 4;
    const int tot = 6*M4 + NX4;
    for (int i = blockIdx.x*blockDim.x + threadIdx.x; i < tot;
         i += gridDim.x*blockDim.x) {
        float4 v;
        int mat, off;
        if (i < 6*M4) {
            mat = i / M4; off = i - mat*M4;
            const float* src = (mat==0)?Wz:(mat==1)?Wr:(mat==2)?Wh:
                               (mat==3)?Uz:(mat==4)?Ur:Uh;
            v = __ldg((const float4*)src + off);
        } else {
            mat = 7; off = i - 6*M4;
            v = __ldg((const float4*)x + off);
        }
        __nv_bfloat16 h0 = __float2bfloat16(v.x), h1 = __float2bfloat16(v.y);
        __nv_bfloat16 h2 = __float2bfloat16(v.z), h3 = __float2bfloat16(v.w);
        __nv_bfloat16 l0 = __float2bfloat16(v.x - __bfloat162float(h0));
        __nv_bfloat16 l1 = __float2bfloat16(v.y - __bfloat162float(h1));
        __nv_bfloat16 l2 = __float2bfloat16(v.z - __bfloat162float(h2));
        __nv_bfloat16 l3 = __float2bfloat16(v.w - __bfloat162float(h3));
        uint2 hp, lp;
        hp.x = ((uint32_t)__bfloat16_as_ushort(h1) << 16) | __bfloat16_as_ushort(h0);
        hp.y = ((uint32_t)__bfloat16_as_ushort(h3) << 16) | __bfloat16_as_ushort(h2);
        lp.x = ((uint32_t)__bfloat16_as_ushort(l1) << 16) | __bfloat16_as_ushort(l0);
        lp.y = ((uint32_t)__bfloat16_as_ushort(l3) << 16) | __bfloat16_as_ushort(l2);
        if (mat < 3) {
            *(uint2*)&g_Wb[0][(size_t)mat*D_*D_ + (size_t)off*4] = hp;
            *(uint2*)&g_Wb[1][(size_t)mat*D_*D_ + (size_t)off*4] = lp;
        } else if (mat < 6) {
            *(uint2*)&g_Ub[0][(size_t)(mat-3)*D_*D_ + (size_t)off*4] = hp;
            *(uint2*)&g_Ub[1][(size_t)(mat-3)*D_*D_ + (size_t)off*4] = lp;
        } else {
            *(uint2*)&g_xb[0][(size_t)off*4] = hp;
            *(uint2*)&g_xb[1][(size_t)off*4] = lp;
        }
    }
}

// ===================== kernel 2: mma.sync GEMM for gx (as R8) ==============
#define GM_THREADS 256
#define ASTRIDE 40
#define PLANE   (128*ASTRIDE)
#define GEMM_SMEM (4*PLANE*2)

__global__ void __launch_bounds__(GM_THREADS, 2)
gemm_kernel(const float* __restrict__ bz, const float* __restrict__ cz,
            const float* __restrict__ br, const float* __restrict__ cr,
            const float* __restrict__ bh, const float* __restrict__ ch)
{
    extern __shared__ __nv_bfloat16 sm[];
    const int tid  = threadIdx.x;
    const int w    = tid >> 5;
    const int lane = tid & 31;
    const int wm   = w >> 2;
    const int wn   = w & 3;
    const int mbase = blockIdx.y * 128;
    const int nbase = blockIdx.x * 128;
    const uint32_t smb = smem_to_u32(sm);

    float acc[4][4][4];
    #pragma unroll
    for (int mf = 0; mf < 4; mf++)
        #pragma unroll
        for (int nf = 0; nf < 4; nf++)
            #pragma unroll
            for (int i = 0; i < 4; i++) acc[mf][nf][i] = 0.0f;

    for (int kc = 0; kc < 32; kc++) {
        #pragma unroll
        for (int it = 0; it < 8; it++) {
            const int idx  = tid + it * GM_THREADS;
            const int part = idx >> 9;
            const int rem  = idx & 511;
            const int row  = rem >> 2;
            const int chk  = rem & 3;
            const uint4* src = (part < 2)
                ? (const uint4*)&g_Wb[part    ][((size_t)(mbase + row) << 10) + kc*32 + chk*8]
                : (const uint4*)&g_xb[part - 2][((size_t)(nbase + row) << 10) + kc*32 + chk*8];
            *(uint4*)&sm[part*PLANE + row*ASTRIDE + chk*8] = __ldg(src);
        }
        __syncthreads();

        #pragma unroll
        for (int h = 0; h < 2; h++) {
            const int k16 = h * 16;
            uint32_t af[4][4], bhf[4][2], blf[4][2];
            #pragma unroll
            for (int mf = 0; mf < 4; mf++) {
                const uint32_t a = smb + 2u*(0*PLANE +
                    (wm*64 + mf*16 + (lane & 15))*ASTRIDE + k16 + (lane >> 4)*8);
                ldsm4(af[mf], a);
            }
            #pragma unroll
            for (int nf = 0; nf < 4; nf++) {
                const uint32_t rc = (wn*32 + nf*8 + (lane & 7))*ASTRIDE + k16 + ((lane >> 3) & 1)*8;
                ldsm2(bhf[nf], smb + 2u*(2*PLANE + rc));
                ldsm2(blf[nf], smb + 2u*(3*PLANE + rc));
            }
            #pragma unroll
            for (int mf = 0; mf < 4; mf++)
                #pragma unroll
                for (int nf = 0; nf < 4; nf++) {
                    mma16816(acc[mf][nf], af[mf], bhf[nf]);
                    mma16816(acc[mf][nf], af[mf], blf[nf]);
                }
            #pragma unroll
            for (int mf = 0; mf < 4; mf++) {
                const uint32_t a = smb + 2u*(1*PLANE +
                    (wm*64 + mf*16 + (lane & 15))*ASTRIDE + k16 + (lane >> 4)*8);
                ldsm4(af[mf], a);
            }
            #pragma unroll
            for (int mf = 0; mf < 4; mf++)
                #pragma unroll
                for (int nf = 0; nf < 4; nf++)
                    mma16816(acc[mf][nf], af[mf], bhf[nf]);
        }
        __syncthreads();
    }

    const int g = mbase >> 10;
    const float* bp = (g == 0) ? bz : (g == 1) ? br : bh;
    const float* cp = (g == 0) ? cz : (g == 1) ? cr : ch;
    #pragma unroll
    for (int mf = 0; mf < 4; mf++) {
        const int row0 = wm*64 + mf*16 + (lane >> 2);
        const int jl0  = (mbase + row0) & 1023;
        const int jl8  = (mbase + row0 + 8) & 1023;
        const float bias0 = bp[jl0] + cp[jl0];
        const float bias8 = bp[jl8] + cp[jl8];
        #pragma unroll
        for (int nf = 0; nf < 4; nf++) {
            const int col0 = wn*32 + nf*8 + (lane & 3)*2;
            #pragma unroll
            for (int cc = 0; cc < 2; cc++) {
                const int n = nbase + col0 + cc;
                const int b = n >> 7;
                const int t = n & 127;
                const size_t base = ((size_t)(g*T_ + t)*B_ + b)*D_;
                g_gx[base + jl0] = acc[mf][nf][cc]     + bias0;
                g_gx[base + jl8] = acc[mf][nf][cc + 2] + bias8;
            }
        }
    }
}

// ===================== kernel 3: persistent recurrence (mma) ===============
__device__ __forceinline__ void grid_barrier(int grp)
{
    __syncthreads();
    if (threadIdx.x == 0) {
        const unsigned gen = ld_acq(&g_bar_gen);   // read BEFORE arriving
        if (atom_inc_acqrel(&g_bar_cnt[grp*32]) == GRPSZ - 1u) {
            st_rlx(&g_bar_cnt[grp*32], 0u);        // ordered by next acq_rel
            if (atom_inc_acqrel(&g_bar_root) == NGRP - 1u) {
                st_rlx(&g_bar_root, 0u);
                atom_inc_acqrel(&g_bar_gen);
            } else {
                while (ld_acq(&g_bar_gen) == gen) { }
            }
        } else {
            while (ld_acq(&g_bar_gen) == gen) { }
        }
    }
    __syncthreads();
}

#define GRU_SMEM (2*NW*512*4)    // 64 KB partials

__global__ void __launch_bounds__(TPB, 1)
gru_kernel(float* __restrict__ out)
{
    extern __shared__ float spar[];     // [2][NW][512]
    __shared__ float sh_z[512];
    __shared__ float sh_h[512];         // canonical fp32 h for CTA's 16 cols

    const int tid  = threadIdx.x;
    const int w    = tid >> 5;
    const int lane = tid & 31;
    const int j0   = blockIdx.x * JPC;
    const int grp  = blockIdx.x >> 3;
    const int gid  = lane >> 2;
    const int tig  = lane & 3;

    // ---- preload U B-fragments (z,r: hi plane only; h: hi+lo)
    uint32_t buz[4][2][2], bur[4][2][2], buh[2][4][2][2];
    #pragma unroll
    for (int nf = 0; nf < 2; nf++) {
        const int jrow = j0 + nf*8 + gid;
        #pragma unroll
        for (int kt = 0; kt < 4; kt++) {
            const int k0 = (w << 6) + (kt << 4) + (tig << 1);
            const size_t rz = ((size_t)(0*1024 + jrow) << 10) + k0;
            const size_t rr = ((size_t)(1*1024 + jrow) << 10) + k0;
            const size_t rh = ((size_t)(2*1024 + jrow) << 10) + k0;
            buz[kt][nf][0] = *(const uint32_t*)&g_Ub[0][rz];
            buz[kt][nf][1] = *(const uint32_t*)&g_Ub[0][rz + 8];
            bur[kt][nf][0] = *(const uint32_t*)&g_Ub[0][rr];
            bur[kt][nf][1] = *(const uint32_t*)&g_Ub[0][rr + 8];
            buh[0][kt][nf][0] = *(const uint32_t*)&g_Ub[0][rh];
            buh[0][kt][nf][1] = *(const uint32_t*)&g_Ub[0][rh + 8];
            buh[1][kt][nf][0] = *(const uint32_t*)&g_Ub[1][rh];
            buh[1][kt][nf][1] = *(const uint32_t*)&g_Ub[1][rh + 8];
        }
    }

    // ---- reduction-thread identity + h/rh scatter pointers (1 per thread)
    const int rb  = tid >> 4;          // batch 0..31
    const int rjj = tid & 15;
    const int rj  = j0 + rjj;
    const uint32_t hoff = hfrag_off(rb, rj);
    const int      half = rj & 1;
    uint16_t* h0p = (uint16_t*)g_hA[0] + (size_t)hoff*2 + half;
    uint16_t* h1p = (uint16_t*)g_hA[1] + (size_t)hoff*2 + half;
    uint16_t* r0p = (uint16_t*)g_rA[0] + (size_t)hoff*2 + half;
    uint16_t* r1p = (uint16_t*)g_rA[1] + (size_t)hoff*2 + half;

    *h0p = 0; *h1p = 0; sh_h[tid] = 0.0f;
    grid_barrier(grp);

    const uint32_t abase = (w << 10) + (lane << 2);

    for (int t = 0; t < T_; t++) {
        const float gxZ = g_gx[((size_t)(0*T_ + t)*B_ + rb)*D_ + rj];
        const float gxR = g_gx[((size_t)(1*T_ + t)*B_ + rb)*D_ + rj];
        const float gxH = g_gx[((size_t)(2*T_ + t)*B_ + rb)*D_ + rj];

        // ================= phase A: z, r =================
        #pragma unroll
        for (int mt = 0; mt < 2; mt++) {
            float cz[2][4], cr[2][4];
            #pragma unroll
            for (int nf = 0; nf < 2; nf++)
                #pragma unroll
                for (int i = 0; i < 4; i++) { cz[nf][i] = 0.0f; cr[nf][i] = 0.0f; }

            uint4 af[4];
            #pragma unroll
            for (int kt = 0; kt < 4; kt++)
                af[kt] = __ldcg((const uint4*)(g_hA[0] + abase + ((kt*2 + mt) << 7)));
            #pragma unroll
            for (int kt = 0; kt < 4; kt++)
                #pragma unroll
                for (int nf = 0; nf < 2; nf++) {
                    mma16816(cz[nf], (const uint32_t*)&af[kt], buz[kt][nf]);
                    mma16816(cr[nf], (const uint32_t*)&af[kt], bur[kt][nf]);
                }
            #pragma unroll
            for (int kt = 0; kt < 4; kt++)
                af[kt] = __ldcg((const uint4*)(g_hA[1] + abase + ((kt*2 + mt) << 7)));
            #pragma unroll
            for (int kt = 0; kt < 4; kt++)
                #pragma unroll
                for (int nf = 0; nf < 2; nf++) {
                    mma16816(cz[nf], (const uint32_t*)&af[kt], buz[kt][nf]);
                    mma16816(cr[nf], (const uint32_t*)&af[kt], bur[kt][nf]);
                }
            const int b0 = mt*16 + gid;
            #pragma unroll
            for (int nf = 0; nf < 2; nf++) {
                const int i0 = b0*16 + nf*8 + tig*2;
                *(float2*)&spar[(0*NW + w)*512 + i0]       = make_float2(cz[nf][0], cz[nf][1]);
                *(float2*)&spar[(0*NW + w)*512 + i0 + 128] = make_float2(cz[nf][2], cz[nf][3]);
                *(float2*)&spar[(1*NW + w)*512 + i0]       = make_float2(cr[nf][0], cr[nf][1]);
                *(float2*)&spar[(1*NW + w)*512 + i0 + 128] = make_float2(cr[nf][2], cr[nf][3]);
            }
        }
        __syncthreads();
        {
            float sz = gxZ, sr = gxR;
            #pragma unroll
            for (int w2 = 0; w2 < NW; w2++) {
                sz += spar[(0*NW + w2)*512 + tid];
                sr += spar[(1*NW + w2)*512 + tid];
            }
            const float z = sigm(sz);
            const float r = sigm(sr);
            sh_z[tid] = z;
            const float rh = r * sh_h[tid];
            const __nv_bfloat16 hi = __float2bfloat16(rh);
            const __nv_bfloat16 lo = __float2bfloat16(rh - __bfloat162float(hi));
            *r0p = __bfloat16_as_ushort(hi);
            *r1p = __bfloat16_as_ushort(lo);
        }
        grid_barrier(grp);

        // ================= phase B: candidate + update =================
        #pragma unroll
        for (int mt = 0; mt < 2; mt++) {
            float ch[2][4];
            #pragma unroll
            for (int nf = 0; nf < 2; nf++)
                #pragma unroll
                for (int i = 0; i < 4; i++) ch[nf][i] = 0.0f;

            uint4 af[4];
            #pragma unroll
            for (int kt = 0; kt < 4; kt++)
                af[kt] = __ldcg((const uint4*)(g_rA[0] + abase + ((kt*2 + mt) << 7)));
            #pragma unroll
            for (int kt = 0; kt < 4; kt++)
                #pragma unroll
                for (int nf = 0; nf < 2; nf++) {
                    mma16816(ch[nf], (const uint32_t*)&af[kt], buh[0][kt][nf]);
                    mma16816(ch[nf], (const uint32_t*)&af[kt], buh[1][kt][nf]);
                }
            #pragma unroll
            for (int kt = 0; kt < 4; kt++)
                af[kt] = __ldcg((const uint4*)(g_rA[1] + abase + ((kt*2 + mt) << 7)));
            #pragma unroll
            for (int kt = 0; kt < 4; kt++)
                #pragma unroll
                for (int nf = 0; nf < 2; nf++)
                    mma16816(ch[nf], (const uint32_t*)&af[kt], buh[0][kt][nf]);

            const int b0 = mt*16 + gid;
            #pragma unroll
            for (int nf = 0; nf < 2; nf++) {
                const int i0 = b0*16 + nf*8 + tig*2;
                *(float2*)&spar[(0*NW + w)*512 + i0]       = make_float2(ch[nf][0], ch[nf][1]);
                *(float2*)&spar[(0*NW + w)*512 + i0 + 128] = make_float2(ch[nf][2], ch[nf][3]);
            }
        }
        __syncthreads();
        {
            float s = gxH;
            #pragma unroll
            for (int w2 = 0; w2 < NW; w2++) s += spar[(0*NW + w2)*512 + tid];
            const float hh   = sigm(s);
            const float hold = sh_h[tid];
            const float hn   = fmaf(sh_z[tid], hh - hold, hold);
            const __nv_bfloat16 hi = __float2bfloat16(hn);
            const __nv_bfloat16 lo = __float2bfloat16(hn - __bfloat162float(hi));
            *h0p = __bfloat16_as_ushort(hi);
            *h1p = __bfloat16_as_ushort(lo);
            // reference reshape: flat output memory layout is (T,B,D)
            out[(size_t)t*(B_*D_) + rb*D_ + rj] = hn;
            sh_h[tid] = hn;
        }
        grid_barrier(grp);
    }
}

// ===================== launch =====================
extern "C" void kernel_launch(void* const* d_in, const int* in_sizes, int n_in,
                              void* d_out, int out_size)
{
    (void)in_sizes; (void)n_in; (void)out_size;
    const float* x  = (const float*)d_in[0];
    const float* Wz = (const float*)d_in[1];
    const float* bz = (const float*)d_in[2];
    const float* Uz = (const float*)d_in[3];
    const float* cz = (const float*)d_in[4];
    const float* Wr = (const float*)d_in[5];
    const float* br = (const float*)d_in[6];
    const float* Ur = (const float*)d_in[7];
    const float* cr = (const float*)d_in[8];
    const float* Wh = (const float*)d_in[9];
    const float* bh = (const float*)d_in[10];
    const float* Uh = (const float*)d_in[11];
    const float* ch = (const float*)d_in[12];
    float* out = (float*)d_out;

    // 1) fused bf16 hi/lo split (W, U, x)
    split_all<<<2048, 256>>>(Wz, Wr, Wh, Uz, Ur, Uh, x);

    // 2) mma.sync GEMM -> g_gx (+bias)
    cudaFuncSetAttribute(gemm_kernel, cudaFuncAttributeMaxDynamicSharedMemorySize,
                         GEMM_SMEM);
    gemm_kernel<<<dim3(32, 24), GM_THREADS, GEMM_SMEM>>>(bz, cz, br, cr, bh, ch);

    // 3) persistent recurrence (mma.sync, weights in registers)
    cudaFuncSetAttribute(gru_kernel, cudaFuncAttributeMaxDynamicSharedMemorySize,
                         GRU_SMEM);
    gru_kernel<<<NCTA, TPB, GRU_SMEM>>>(out);
}

// round 14
// speedup vs baseline: 1.8901x; 1.2992x over previous
#include <cuda_runtime.h>
#include <cuda_bf16.h>
#include <cstdint>

// ---------------------------------------------------------------------------
// manyToManyGRU: B=32, T=128, DIN=DOUT=1024, fp32.
//
// R12 vs R11 (1493us, neutral): the centralized grid barrier is replaced by
// point-to-point per-CTA phase flags. Warp w consumes h/rh only for
// k in [64w, 64w+64) = j-slices of producer CTAs 4w..4w+3, so each warp
// polls just 4 monotone flags (producer: stores -> syncthreads ->
// fence.acq_rel.gpu -> st.release flag). No resets (flags zeroed after one
// final cleanup barrier so graph replays see zeros). Uh weight fragments
// moved from registers to padded SMEM (conflict-free LDS) to end the
// 128-reg ceiling pressure. Split + gx GEMM kernels unchanged from R11.
// ---------------------------------------------------------------------------

#define B_   32
#define T_   128
#define D_   1024
#define NCTA 64
#define JPC  16
#define TPB  512
#define NW   16
#define NGRP 8
#define GRPSZ 8

// gx layout: [(g*T + t)*B + b]*D + j
__device__ __align__(16) float g_gx[(size_t)3*T_*B_*D_];
// h / rh broadcast planes, fragment-linear (see hfrag_off): [plane][b32 idx]
__device__ __align__(16) uint32_t g_hA[2][NW*1024];
__device__ __align__(16) uint32_t g_rA[2][NW*1024];
__device__ __align__(128) unsigned g_bar_cnt[NGRP*32];
__device__ unsigned g_bar_root = 0;
__device__ unsigned g_bar_gen  = 0;
// per-CTA monotone phase flags (128B padded)
__device__ __align__(128) unsigned g_flagH[NCTA*32];
__device__ __align__(128) unsigned g_flagR[NCTA*32];

// bf16 split planes
__device__ __align__(16) __nv_bfloat16 g_Wb[2][(size_t)3*D_*D_];  // [(g*1024+j)*1024+k]
__device__ __align__(16) __nv_bfloat16 g_Ub[2][(size_t)3*D_*D_];  // [(g*1024+j)*1024+k]
__device__ __align__(16) __nv_bfloat16 g_xb[2][(size_t)B_*T_*D_]; // [(b*T+t)*1024+k]

__device__ __forceinline__ float sigm(float v) { return 1.0f / (1.0f + __expf(-v)); }

__device__ __forceinline__ uint32_t smem_to_u32(const void* p) {
    uint32_t a;
    asm("{ .reg .u64 t; cvta.to.shared.u64 t, %1; cvt.u32.u64 %0, t; }"
        : "=r"(a) : "l"(p));
    return a;
}
__device__ __forceinline__ void ldsm4(uint32_t* r, uint32_t a) {
    asm volatile("ldmatrix.sync.aligned.m8n8.x4.shared.b16 {%0,%1,%2,%3}, [%4];"
        : "=r"(r[0]), "=r"(r[1]), "=r"(r[2]), "=r"(r[3]) : "r"(a));
}
__device__ __forceinline__ void ldsm2(uint32_t* r, uint32_t a) {
    asm volatile("ldmatrix.sync.aligned.m8n8.x2.shared.b16 {%0,%1}, [%2];"
        : "=r"(r[0]), "=r"(r[1]) : "r"(a));
}
__device__ __forceinline__ void mma16816(float* c, const uint32_t* a, const uint32_t* b) {
    asm volatile("mma.sync.aligned.m16n8k16.row.col.f32.bf16.bf16.f32 "
        "{%0,%1,%2,%3}, {%4,%5,%6,%7}, {%8,%9}, {%0,%1,%2,%3};"
        : "+f"(c[0]), "+f"(c[1]), "+f"(c[2]), "+f"(c[3])
        : "r"(a[0]), "r"(a[1]), "r"(a[2]), "r"(a[3]), "r"(b[0]), "r"(b[1]));
}

// memory-order primitives
__device__ __forceinline__ unsigned ld_acq(const unsigned* p) {
    unsigned v;
    asm volatile("ld.acquire.gpu.global.u32 %0, [%1];" : "=r"(v) : "l"(p) : "memory");
    return v;
}
__device__ __forceinline__ unsigned atom_inc_acqrel(unsigned* p) {
    unsigned o;
    asm volatile("atom.acq_rel.gpu.global.add.u32 %0, [%1], 1;" : "=r"(o) : "l"(p) : "memory");
    return o;
}
__device__ __forceinline__ void st_rlx(unsigned* p, unsigned v) {
    asm volatile("st.relaxed.gpu.global.u32 [%0], %1;" :: "l"(p), "r"(v) : "memory");
}
__device__ __forceinline__ void st_rel(unsigned* p, unsigned v) {
    asm volatile("st.release.gpu.global.u32 [%0], %1;" :: "l"(p), "r"(v) : "memory");
}
__device__ __forceinline__ void fence_acqrel_gpu() {
    asm volatile("fence.acq_rel.gpu;" ::: "memory");
}

// fragment-linear b32 index of value (b, k) inside the h/rh planes.
__device__ __forceinline__ uint32_t hfrag_off(int b, int k) {
    const int w  = k >> 6;
    const int kl = k & 63;
    const int kt = kl >> 4;
    const int kin = kl & 15;
    const int mt = b >> 4;
    const int rr = b & 15;
    const int lane = (rr & 7)*4 + ((kin & 7) >> 1);
    const int reg  = (rr >> 3) | ((kin >> 3) << 1);
    return (uint32_t)(w*1024 + ((kt*2 + mt)*32 + lane)*4 + reg);
}

// ===================== kernel 1: fused fp32 -> bf16 (hi,lo) split ==========
__global__ void split_all(const float* __restrict__ Wz, const float* __restrict__ Wr,
                          const float* __restrict__ Wh, const float* __restrict__ Uz,
                          const float* __restrict__ Ur, const float* __restrict__ Uh,
                          const float* __restrict__ x)
{
    const int M4  = (D_*D_) / 4;
    const int NX4 = (B_*T_*D_) / 4;
    const int tot = 6*M4 + NX4;
    for (int i = blockIdx.x*blockDim.x + threadIdx.x; i < tot;
         i += gridDim.x*blockDim.x) {
        float4 v;
        int mat, off;
        if (i < 6*M4) {
            mat = i / M4; off = i - mat*M4;
            const float* src = (mat==0)?Wz:(mat==1)?Wr:(mat==2)?Wh:
                               (mat==3)?Uz:(mat==4)?Ur:Uh;
            v = __ldg((const float4*)src + off);
        } else {
            mat = 7; off = i - 6*M4;
            v = __ldg((const float4*)x + off);
        }
        __nv_bfloat16 h0 = __float2bfloat16(v.x), h1 = __float2bfloat16(v.y);
        __nv_bfloat16 h2 = __float2bfloat16(v.z), h3 = __float2bfloat16(v.w);
        __nv_bfloat16 l0 = __float2bfloat16(v.x - __bfloat162float(h0));
        __nv_bfloat16 l1 = __float2bfloat16(v.y - __bfloat162float(h1));
        __nv_bfloat16 l2 = __float2bfloat16(v.z - __bfloat162float(h2));
        __nv_bfloat16 l3 = __float2bfloat16(v.w - __bfloat162float(h3));
        uint2 hp, lp;
        hp.x = ((uint32_t)__bfloat16_as_ushort(h1) << 16) | __bfloat16_as_ushort(h0);
        hp.y = ((uint32_t)__bfloat16_as_ushort(h3) << 16) | __bfloat16_as_ushort(h2);
        lp.x = ((uint32_t)__bfloat16_as_ushort(l1) << 16) | __bfloat16_as_ushort(l0);
        lp.y = ((uint32_t)__bfloat16_as_ushort(l3) << 16) | __bfloat16_as_ushort(l2);
        if (mat < 3) {
            *(uint2*)&g_Wb[0][(size_t)mat*D_*D_ + (size_t)off*4] = hp;
            *(uint2*)&g_Wb[1][(size_t)mat*D_*D_ + (size_t)off*4] = lp;
        } else if (mat < 6) {
            *(uint2*)&g_Ub[0][(size_t)(mat-3)*D_*D_ + (size_t)off*4] = hp;
            *(uint2*)&g_Ub[1][(size_t)(mat-3)*D_*D_ + (size_t)off*4] = lp;
        } else {
            *(uint2*)&g_xb[0][(size_t)off*4] = hp;
            *(uint2*)&g_xb[1][(size_t)off*4] = lp;
        }
    }
}

// ===================== kernel 2: mma.sync GEMM for gx (as R8) ==============
#define GM_THREADS 256
#define ASTRIDE 40
#define PLANE   (128*ASTRIDE)
#define GEMM_SMEM (4*PLANE*2)

__global__ void __launch_bounds__(GM_THREADS, 2)
gemm_kernel(const float* __restrict__ bz, const float* __restrict__ cz,
            const float* __restrict__ br, const float* __restrict__ cr,
            const float* __restrict__ bh, const float* __restrict__ ch)
{
    extern __shared__ __nv_bfloat16 sm[];
    const int tid  = threadIdx.x;
    const int w    = tid >> 5;
    const int lane = tid & 31;
    const int wm   = w >> 2;
    const int wn   = w & 3;
    const int mbase = blockIdx.y * 128;
    const int nbase = blockIdx.x * 128;
    const uint32_t smb = smem_to_u32(sm);

    float acc[4][4][4];
    #pragma unroll
    for (int mf = 0; mf < 4; mf++)
        #pragma unroll
        for (int nf = 0; nf < 4; nf++)
            #pragma unroll
            for (int i = 0; i < 4; i++) acc[mf][nf][i] = 0.0f;

    for (int kc = 0; kc < 32; kc++) {
        #pragma unroll
        for (int it = 0; it < 8; it++) {
            const int idx  = tid + it * GM_THREADS;
            const int part = idx >> 9;
            const int rem  = idx & 511;
            const int row  = rem >> 2;
            const int chk  = rem & 3;
            const uint4* src = (part < 2)
                ? (const uint4*)&g_Wb[part    ][((size_t)(mbase + row) << 10) + kc*32 + chk*8]
                : (const uint4*)&g_xb[part - 2][((size_t)(nbase + row) << 10) + kc*32 + chk*8];
            *(uint4*)&sm[part*PLANE + row*ASTRIDE + chk*8] = __ldg(src);
        }
        __syncthreads();

        #pragma unroll
        for (int h = 0; h < 2; h++) {
            const int k16 = h * 16;
            uint32_t af[4][4], bhf[4][2], blf[4][2];
            #pragma unroll
            for (int mf = 0; mf < 4; mf++) {
                const uint32_t a = smb + 2u*(0*PLANE +
                    (wm*64 + mf*16 + (lane & 15))*ASTRIDE + k16 + (lane >> 4)*8);
                ldsm4(af[mf], a);
            }
            #pragma unroll
            for (int nf = 0; nf < 4; nf++) {
                const uint32_t rc = (wn*32 + nf*8 + (lane & 7))*ASTRIDE + k16 + ((lane >> 3) & 1)*8;
                ldsm2(bhf[nf], smb + 2u*(2*PLANE + rc));
                ldsm2(blf[nf], smb + 2u*(3*PLANE + rc));
            }
            #pragma unroll
            for (int mf = 0; mf < 4; mf++)
                #pragma unroll
                for (int nf = 0; nf < 4; nf++) {
                    mma16816(acc[mf][nf], af[mf], bhf[nf]);
                    mma16816(acc[mf][nf], af[mf], blf[nf]);
                }
            #pragma unroll
            for (int mf = 0; mf < 4; mf++) {
                const uint32_t a = smb + 2u*(1*PLANE +
                    (wm*64 + mf*16 + (lane & 15))*ASTRIDE + k16 + (lane >> 4)*8);
                ldsm4(af[mf], a);
            }
            #pragma unroll
            for (int mf = 0; mf < 4; mf++)
                #pragma unroll
                for (int nf = 0; nf < 4; nf++)
                    mma16816(acc[mf][nf], af[mf], bhf[nf]);
        }
        __syncthreads();
    }

    const int g = mbase >> 10;
    const float* bp = (g == 0) ? bz : (g == 1) ? br : bh;
    const float* cp = (g == 0) ? cz : (g == 1) ? cr : ch;
    #pragma unroll
    for (int mf = 0; mf < 4; mf++) {
        const int row0 = wm*64 + mf*16 + (lane >> 2);
        const int jl0  = (mbase + row0) & 1023;
        const int jl8  = (mbase + row0 + 8) & 1023;
        const float bias0 = bp[jl0] + cp[jl0];
        const float bias8 = bp[jl8] + cp[jl8];
        #pragma unroll
        for (int nf = 0; nf < 4; nf++) {
            const int col0 = wn*32 + nf*8 + (lane & 3)*2;
            #pragma unroll
            for (int cc = 0; cc < 2; cc++) {
                const int n = nbase + col0 + cc;
                const int b = n >> 7;
                const int t = n & 127;
                const size_t base = ((size_t)(g*T_ + t)*B_ + b)*D_;
                g_gx[base + jl0] = acc[mf][nf][cc]     + bias0;
                g_gx[base + jl8] = acc[mf][nf][cc + 2] + bias8;
            }
        }
    }
}

// ===================== kernel 3: persistent recurrence (flags) =============
__device__ __forceinline__ void grid_barrier(int grp)
{
    __syncthreads();
    if (threadIdx.x == 0) {
        const unsigned gen = ld_acq(&g_bar_gen);
        if (atom_inc_acqrel(&g_bar_cnt[grp*32]) == GRPSZ - 1u) {
            st_rlx(&g_bar_cnt[grp*32], 0u);
            if (atom_inc_acqrel(&g_bar_root) == NGRP - 1u) {
                st_rlx(&g_bar_root, 0u);
                atom_inc_acqrel(&g_bar_gen);
            } else {
                while (ld_acq(&g_bar_gen) == gen) { }
            }
        } else {
            while (ld_acq(&g_bar_gen) == gen) { }
        }
    }
    __syncthreads();
}

#define UHSTRIDE 1032                      // bf16 elems; pad -> conflict-free LDS
#define UHP (JPC*UHSTRIDE)                 // elems per plane
#define GRU_SMEM (2*NW*512*4 + 2*UHP*2)    // 64KB partials + 66048B Uh

__global__ void __launch_bounds__(TPB, 1)
gru_kernel(float* __restrict__ out)
{
    extern __shared__ char dyn[];
    float* spar = (float*)dyn;                                   // [2][NW][512]
    __nv_bfloat16* shUh = (__nv_bfloat16*)(dyn + 2*NW*512*4);    // [2][JPC][1032]
    __shared__ float sh_z[512];
    __shared__ float sh_h[512];

    const int tid  = threadIdx.x;
    const int w    = tid >> 5;
    const int lane = tid & 31;
    const int cta  = blockIdx.x;
    const int j0   = cta * JPC;
    const int grp  = cta >> 3;
    const int gid  = lane >> 2;
    const int tig  = lane & 3;

    // ---- stage Uh (hi,lo) rows j0..j0+15 into padded SMEM
    for (int i = tid; i < 2*JPC*512; i += TPB) {     // u32 units
        const int plane = i >> 13;                   // JPC*512 = 8192
        const int rem   = i & 8191;
        const int row   = rem >> 9;
        const int k2    = rem & 511;
        const uint32_t v = *(const uint32_t*)
            &g_Ub[plane][((size_t)(2*1024 + j0 + row) << 10) + (k2 << 1)];
        *(uint32_t*)&shUh[plane*UHP + row*UHSTRIDE + (k2 << 1)] = v;
    }

    // ---- preload Uz, Ur B-fragments (hi plane only) into registers
    uint32_t buz[4][2][2], bur[4][2][2];
    #pragma unroll
    for (int nf = 0; nf < 2; nf++) {
        const int jrow = j0 + nf*8 + gid;
        #pragma unroll
        for (int kt = 0; kt < 4; kt++) {
            const int k0 = (w << 6) + (kt << 4) + (tig << 1);
            const size_t rz = ((size_t)(0*1024 + jrow) << 10) + k0;
            const size_t rr = ((size_t)(1*1024 + jrow) << 10) + k0;
            buz[kt][nf][0] = *(const uint32_t*)&g_Ub[0][rz];
            buz[kt][nf][1] = *(const uint32_t*)&g_Ub[0][rz + 8];
            bur[kt][nf][0] = *(const uint32_t*)&g_Ub[0][rr];
            bur[kt][nf][1] = *(const uint32_t*)&g_Ub[0][rr + 8];
        }
    }

    // ---- per-thread (b, j) identity + scatter pointers
    const int rb  = tid >> 4;
    const int rjj = tid & 15;
    const int rj  = j0 + rjj;
    const uint32_t hoff = hfrag_off(rb, rj);
    const int      half = rj & 1;
    uint16_t* h0p = (uint16_t*)g_hA[0] + (size_t)hoff*2 + half;
    uint16_t* h1p = (uint16_t*)g_hA[1] + (size_t)hoff*2 + half;
    uint16_t* r0p = (uint16_t*)g_rA[0] + (size_t)hoff*2 + half;
    uint16_t* r1p = (uint16_t*)g_rA[1] + (size_t)hoff*2 + half;

    // ---- publish h0 = 0
    *h0p = 0; *h1p = 0; sh_h[tid] = 0.0f;
    __syncthreads();
    if (tid == 0) { fence_acqrel_gpu(); st_rel(&g_flagH[cta*32], 1u); }

    const uint32_t abase = (w << 10) + (lane << 2);
    // warp w's 4 producer flags (CTAs 4w .. 4w+3)
    const unsigned* myFH = &g_flagH[((w << 2) + (lane & 3)) * 32];
    const unsigned* myFR = &g_flagR[((w << 2) + (lane & 3)) * 32];
    const bool poller = (lane < 4);

    for (int t = 0; t < T_; t++) {
        const float gxZ = g_gx[((size_t)(0*T_ + t)*B_ + rb)*D_ + rj];
        const float gxR = g_gx[((size_t)(1*T_ + t)*B_ + rb)*D_ + rj];
        const float gxH = g_gx[((size_t)(2*T_ + t)*B_ + rb)*D_ + rj];

        // ================= phase A: z, r =================
        if (poller) { const unsigned tgt = (unsigned)(t + 1);
                      while (ld_acq(myFH) < tgt) { } }
        __syncwarp();

        #pragma unroll
        for (int mt = 0; mt < 2; mt++) {
            float cz[2][4], cr[2][4];
            #pragma unroll
            for (int nf = 0; nf < 2; nf++)
                #pragma unroll
                for (int i = 0; i < 4; i++) { cz[nf][i] = 0.0f; cr[nf][i] = 0.0f; }

            uint4 af[4];
            #pragma unroll
            for (int kt = 0; kt < 4; kt++)
                af[kt] = __ldcg((const uint4*)(g_hA[0] + abase + ((kt*2 + mt) << 7)));
            #pragma unroll
            for (int kt = 0; kt < 4; kt++)
                #pragma unroll
                for (int nf = 0; nf < 2; nf++) {
                    mma16816(cz[nf], (const uint32_t*)&af[kt], buz[kt][nf]);
                    mma16816(cr[nf], (const uint32_t*)&af[kt], bur[kt][nf]);
                }
            #pragma unroll
            for (int kt = 0; kt < 4; kt++)
                af[kt] = __ldcg((const uint4*)(g_hA[1] + abase + ((kt*2 + mt) << 7)));
            #pragma unroll
            for (int kt = 0; kt < 4; kt++)
                #pragma unroll
                for (int nf = 0; nf < 2; nf++) {
                    mma16816(cz[nf], (const uint32_t*)&af[kt], buz[kt][nf]);
                    mma16816(cr[nf], (const uint32_t*)&af[kt], bur[kt][nf]);
                }
            const int b0 = mt*16 + gid;
            #pragma unroll
            for (int nf = 0; nf < 2; nf++) {
                const int i0 = b0*16 + nf*8 + tig*2;
                *(float2*)&spar[(0*NW + w)*512 + i0]       = make_float2(cz[nf][0], cz[nf][1]);
                *(float2*)&spar[(0*NW + w)*512 + i0 + 128] = make_float2(cz[nf][2], cz[nf][3]);
                *(float2*)&spar[(1*NW + w)*512 + i0]       = make_float2(cr[nf][0], cr[nf][1]);
                *(float2*)&spar[(1*NW + w)*512 + i0 + 128] = make_float2(cr[nf][2], cr[nf][3]);
            }
        }
        __syncthreads();
        {
            float sz = gxZ, sr = gxR;
            #pragma unroll
            for (int w2 = 0; w2 < NW; w2++) {
                sz += spar[(0*NW + w2)*512 + tid];
                sr += spar[(1*NW + w2)*512 + tid];
            }
            const float z = sigm(sz);
            const float r = sigm(sr);
            sh_z[tid] = z;
            const float rh = r * sh_h[tid];
            const __nv_bfloat16 hi = __float2bfloat16(rh);
            const __nv_bfloat16 lo = __float2bfloat16(rh - __bfloat162float(hi));
            *r0p = __bfloat16_as_ushort(hi);
            *r1p = __bfloat16_as_ushort(lo);
        }
        __syncthreads();
        if (tid == 0) { fence_acqrel_gpu(); st_rel(&g_flagR[cta*32], (unsigned)(t + 1)); }

        // ================= phase B: candidate + update =================
        if (poller) { const unsigned tgt = (unsigned)(t + 1);
                      while (ld_acq(myFR) < tgt) { } }
        __syncwarp();

        #pragma unroll
        for (int mt = 0; mt < 2; mt++) {
            float ch[2][4];
            #pragma unroll
            for (int nf = 0; nf < 2; nf++)
                #pragma unroll
                for (int i = 0; i < 4; i++) ch[nf][i] = 0.0f;

            uint4 afh[4], afl[4];
            #pragma unroll
            for (int kt = 0; kt < 4; kt++) {
                afh[kt] = __ldcg((const uint4*)(g_rA[0] + abase + ((kt*2 + mt) << 7)));
                afl[kt] = __ldcg((const uint4*)(g_rA[1] + abase + ((kt*2 + mt) << 7)));
            }
            #pragma unroll
            for (int kt = 0; kt < 4; kt++) {
                const int kcol = (w << 6) + (kt << 4) + (tig << 1);
                #pragma unroll
                for (int nf = 0; nf < 2; nf++) {
                    const __nv_bfloat16* bp = shUh + (nf*8 + gid)*UHSTRIDE + kcol;
                    uint32_t bh[2], bl[2];
                    bh[0] = *(const uint32_t*)bp;
                    bh[1] = *(const uint32_t*)(bp + 8);
                    bl[0] = *(const uint32_t*)(bp + UHP);
                    bl[1] = *(const uint32_t*)(bp + UHP + 8);
                    mma16816(ch[nf], (const uint32_t*)&afh[kt], bh);
                    mma16816(ch[nf], (const uint32_t*)&afh[kt], bl);
                    mma16816(ch[nf], (const uint32_t*)&afl[kt], bh);
                }
            }
            const int b0 = mt*16 + gid;
            #pragma unroll
            for (int nf = 0; nf < 2; nf++) {
                const int i0 = b0*16 + nf*8 + tig*2;
                *(float2*)&spar[(0*NW + w)*512 + i0]       = make_float2(ch[nf][0], ch[nf][1]);
                *(float2*)&spar[(0*NW + w)*512 + i0 + 128] = make_float2(ch[nf][2], ch[nf][3]);
            }
        }
        __syncthreads();
        {
            float s = gxH;
            #pragma unroll
            for (int w2 = 0; w2 < NW; w2++) s += spar[(0*NW + w2)*512 + tid];
            const float hh   = sigm(s);
            const float hold = sh_h[tid];
            const float hn   = fmaf(sh_z[tid], hh - hold, hold);
            const __nv_bfloat16 hi = __float2bfloat16(hn);
            const __nv_bfloat16 lo = __float2bfloat16(hn - __bfloat162float(hi));
            *h0p = __bfloat16_as_ushort(hi);
            *h1p = __bfloat16_as_ushort(lo);
            // reference reshape: flat output memory layout is (T,B,D)
            out[(size_t)t*(B_*D_) + rb*D_ + rj] = hn;
            sh_h[tid] = hn;
        }
        __syncthreads();
        if (tid == 0) { fence_acqrel_gpu(); st_rel(&g_flagH[cta*32], (unsigned)(t + 2)); }
    }

    // ---- cleanup: quiesce, then zero own flags so graph replays restart
    grid_barrier(grp);
    if (tid == 0) {
        st_rlx(&g_flagH[cta*32], 0u);
        st_rlx(&g_flagR[cta*32], 0u);
    }
}

// ===================== launch =====================
extern "C" void kernel_launch(void* const* d_in, const int* in_sizes, int n_in,
                              void* d_out, int out_size)
{
    (void)in_sizes; (void)n_in; (void)out_size;
    const float* x  = (const float*)d_in[0];
    const float* Wz = (const float*)d_in[1];
    const float* bz = (const float*)d_in[2];
    const float* Uz = (const float*)d_in[3];
    const float* cz = (const float*)d_in[4];
    const float* Wr = (const float*)d_in[5];
    const float* br = (const float*)d_in[6];
    const float* Ur = (const float*)d_in[7];
    const float* cr = (const float*)d_in[8];
    const float* Wh = (const float*)d_in[9];
    const float* bh = (const float*)d_in[10];
    const float* Uh = (const float*)d_in[11];
    const float* ch = (const float*)d_in[12];
    float* out = (float*)d_out;

    // 1) fused bf16 hi/lo split (W, U, x)
    split_all<<<2048, 256>>>(Wz, Wr, Wh, Uz, Ur, Uh, x);

    // 2) mma.sync GEMM -> g_gx (+bias)
    cudaFuncSetAttribute(gemm_kernel, cudaFuncAttributeMaxDynamicSharedMemorySize,
                         GEMM_SMEM);
    gemm_kernel<<<dim3(32, 24), GM_THREADS, GEMM_SMEM>>>(bz, cz, br, cr, bh, ch);

    // 3) persistent recurrence (p2p flags, no global barrier in the loop)
    cudaFuncSetAttribute(gru_kernel, cudaFuncAttributeMaxDynamicSharedMemorySize,
                         GRU_SMEM);
    gru_kernel<<<NCTA, TPB, GRU_SMEM>>>(out);
}

// round 15
// speedup vs baseline: 2.1050x; 1.1137x over previous
#include <cuda_runtime.h>
#include <cuda_bf16.h>
#include <cstdint>

// ---------------------------------------------------------------------------
// manyToManyGRU: B=32, T=128, DIN=DOUT=1024, fp32.
//
// R14 vs R13 (1149us):
//   - h / rh broadcast is a SINGLE bf16 plane (hi only). Error from dropping
//     the lo-planes is the same 2^-9 scale as the already-dropped U-lo terms
//     (measured 3.4e-5) -> predicted ~5-8e-5, far under the 1e-3 gate.
//     Consumer loads halve; phase-A mma 64->32/warp; phase-B 48->32/warp.
//   - Publication is coalesced: a CTA's (32b x 16j) slice = two contiguous
//     512B fragment blocks; values pair up via shfl.xor(1) and even threads
//     store packed u32 -> each warp's stores hit ONE 128B line (was scattered
//     u16s). Release-fence drain cost collapses.
//   - Flags/gemm/split unchanged from R13.
// ---------------------------------------------------------------------------

#define B_   32
#define T_   128
#define D_   1024
#define NCTA 64
#define JPC  16
#define TPB  512
#define NW   16
#define NGRP 8
#define GRPSZ 8

// gx layout: [(g*T + t)*B + b]*D + j
__device__ __align__(16) float g_gx[(size_t)3*T_*B_*D_];
// h / rh broadcast planes (bf16-hi only), fragment-linear (see hfrag note)
__device__ __align__(16) uint32_t g_hA[NW*1024];
__device__ __align__(16) uint32_t g_rA[NW*1024];
__device__ __align__(128) unsigned g_bar_cnt[NGRP*32];
__device__ unsigned g_bar_root = 0;
__device__ unsigned g_bar_gen  = 0;
// per-CTA monotone phase flags (128B padded)
__device__ __align__(128) unsigned g_flagH[NCTA*32];
__device__ __align__(128) unsigned g_flagR[NCTA*32];

// bf16 split planes
__device__ __align__(16) __nv_bfloat16 g_Wb[2][(size_t)3*D_*D_];  // [(g*1024+j)*1024+k]
__device__ __align__(16) __nv_bfloat16 g_Ub[2][(size_t)3*D_*D_];  // [(g*1024+j)*1024+k]
__device__ __align__(16) __nv_bfloat16 g_xb[2][(size_t)B_*T_*D_]; // [(b*T+t)*1024+k]

__device__ __forceinline__ float sigm(float v) { return 1.0f / (1.0f + __expf(-v)); }

__device__ __forceinline__ uint32_t smem_to_u32(const void* p) {
    uint32_t a;
    asm("{ .reg .u64 t; cvta.to.shared.u64 t, %1; cvt.u32.u64 %0, t; }"
        : "=r"(a) : "l"(p));
    return a;
}
__device__ __forceinline__ void ldsm4(uint32_t* r, uint32_t a) {
    asm volatile("ldmatrix.sync.aligned.m8n8.x4.shared.b16 {%0,%1,%2,%3}, [%4];"
        : "=r"(r[0]), "=r"(r[1]), "=r"(r[2]), "=r"(r[3]) : "r"(a));
}
__device__ __forceinline__ void ldsm2(uint32_t* r, uint32_t a) {
    asm volatile("ldmatrix.sync.aligned.m8n8.x2.shared.b16 {%0,%1}, [%2];"
        : "=r"(r[0]), "=r"(r[1]) : "r"(a));
}
__device__ __forceinline__ void mma16816(float* c, const uint32_t* a, const uint32_t* b) {
    asm volatile("mma.sync.aligned.m16n8k16.row.col.f32.bf16.bf16.f32 "
        "{%0,%1,%2,%3}, {%4,%5,%6,%7}, {%8,%9}, {%0,%1,%2,%3};"
        : "+f"(c[0]), "+f"(c[1]), "+f"(c[2]), "+f"(c[3])
        : "r"(a[0]), "r"(a[1]), "r"(a[2]), "r"(a[3]), "r"(b[0]), "r"(b[1]));
}

// memory-order primitives
__device__ __forceinline__ unsigned ld_acq(const unsigned* p) {
    unsigned v;
    asm volatile("ld.acquire.gpu.global.u32 %0, [%1];" : "=r"(v) : "l"(p) : "memory");
    return v;
}
__device__ __forceinline__ unsigned atom_inc_acqrel(unsigned* p) {
    unsigned o;
    asm volatile("atom.acq_rel.gpu.global.add.u32 %0, [%1], 1;" : "=r"(o) : "l"(p) : "memory");
    return o;
}
__device__ __forceinline__ void st_rlx(unsigned* p, unsigned v) {
    asm volatile("st.relaxed.gpu.global.u32 [%0], %1;" :: "l"(p), "r"(v) : "memory");
}
__device__ __forceinline__ void st_rel(unsigned* p, unsigned v) {
    asm volatile("st.release.gpu.global.u32 [%0], %1;" :: "l"(p), "r"(v) : "memory");
}
__device__ __forceinline__ void fence_acqrel_gpu() {
    asm volatile("fence.acq_rel.gpu;" ::: "memory");
}

// ===================== kernel 1: fused fp32 -> bf16 (hi,lo) split ==========
__global__ void split_all(const float* __restrict__ Wz, const float* __restrict__ Wr,
                          const float* __restrict__ Wh, const float* __restrict__ Uz,
                          const float* __restrict__ Ur, const float* __restrict__ Uh,
                          const float* __restrict__ x)
{
    const int M4  = (D_*D_) / 4;
    const int NX4 = (B_*T_*D_) / 4;
    const int tot = 6*M4 + NX4;
    for (int i = blockIdx.x*blockDim.x + threadIdx.x; i < tot;
         i += gridDim.x*blockDim.x) {
        float4 v;
        int mat, off;
        if (i < 6*M4) {
            mat = i / M4; off = i - mat*M4;
            const float* src = (mat==0)?Wz:(mat==1)?Wr:(mat==2)?Wh:
                               (mat==3)?Uz:(mat==4)?Ur:Uh;
            v = __ldg((const float4*)src + off);
        } else {
            mat = 7; off = i - 6*M4;
            v = __ldg((const float4*)x + off);
        }
        __nv_bfloat16 h0 = __float2bfloat16(v.x), h1 = __float2bfloat16(v.y);
        __nv_bfloat16 h2 = __float2bfloat16(v.z), h3 = __float2bfloat16(v.w);
        __nv_bfloat16 l0 = __float2bfloat16(v.x - __bfloat162float(h0));
        __nv_bfloat16 l1 = __float2bfloat16(v.y - __bfloat162float(h1));
        __nv_bfloat16 l2 = __float2bfloat16(v.z - __bfloat162float(h2));
        __nv_bfloat16 l3 = __float2bfloat16(v.w - __bfloat162float(h3));
        uint2 hp, lp;
        hp.x = ((uint32_t)__bfloat16_as_ushort(h1) << 16) | __bfloat16_as_ushort(h0);
        hp.y = ((uint32_t)__bfloat16_as_ushort(h3) << 16) | __bfloat16_as_ushort(h2);
        lp.x = ((uint32_t)__bfloat16_as_ushort(l1) << 16) | __bfloat16_as_ushort(l0);
        lp.y = ((uint32_t)__bfloat16_as_ushort(l3) << 16) | __bfloat16_as_ushort(l2);
        if (mat < 3) {
            *(uint2*)&g_Wb[0][(size_t)mat*D_*D_ + (size_t)off*4] = hp;
            *(uint2*)&g_Wb[1][(size_t)mat*D_*D_ + (size_t)off*4] = lp;
        } else if (mat < 6) {
            *(uint2*)&g_Ub[0][(size_t)(mat-3)*D_*D_ + (size_t)off*4] = hp;
            *(uint2*)&g_Ub[1][(size_t)(mat-3)*D_*D_ + (size_t)off*4] = lp;
        } else {
            *(uint2*)&g_xb[0][(size_t)off*4] = hp;
            *(uint2*)&g_xb[1][(size_t)off*4] = lp;
        }
    }
}

// ===================== kernel 2: mma.sync GEMM for gx (as R8) ==============
#define GM_THREADS 256
#define ASTRIDE 40
#define PLANE   (128*ASTRIDE)
#define GEMM_SMEM (4*PLANE*2)

__global__ void __launch_bounds__(GM_THREADS, 2)
gemm_kernel(const float* __restrict__ bz, const float* __restrict__ cz,
            const float* __restrict__ br, const float* __restrict__ cr,
            const float* __restrict__ bh, const float* __restrict__ ch)
{
    extern __shared__ __nv_bfloat16 sm[];
    const int tid  = threadIdx.x;
    const int w    = tid >> 5;
    const int lane = tid & 31;
    const int wm   = w >> 2;
    const int wn   = w & 3;
    const int mbase = blockIdx.y * 128;
    const int nbase = blockIdx.x * 128;
    const uint32_t smb = smem_to_u32(sm);

    float acc[4][4][4];
    #pragma unroll
    for (int mf = 0; mf < 4; mf++)
        #pragma unroll
        for (int nf = 0; nf < 4; nf++)
            #pragma unroll
            for (int i = 0; i < 4; i++) acc[mf][nf][i] = 0.0f;

    for (int kc = 0; kc < 32; kc++) {
        #pragma unroll
        for (int it = 0; it < 8; it++) {
            const int idx  = tid + it * GM_THREADS;
            const int part = idx >> 9;
            const int rem  = idx & 511;
            const int row  = rem >> 2;
            const int chk  = rem & 3;
            const uint4* src = (part < 2)
                ? (const uint4*)&g_Wb[part    ][((size_t)(mbase + row) << 10) + kc*32 + chk*8]
                : (const uint4*)&g_xb[part - 2][((size_t)(nbase + row) << 10) + kc*32 + chk*8];
            *(uint4*)&sm[part*PLANE + row*ASTRIDE + chk*8] = __ldg(src);
        }
        __syncthreads();

        #pragma unroll
        for (int h = 0; h < 2; h++) {
            const int k16 = h * 16;
            uint32_t af[4][4], bhf[4][2], blf[4][2];
            #pragma unroll
            for (int mf = 0; mf < 4; mf++) {
                const uint32_t a = smb + 2u*(0*PLANE +
                    (wm*64 + mf*16 + (lane & 15))*ASTRIDE + k16 + (lane >> 4)*8);
                ldsm4(af[mf], a);
            }
            #pragma unroll
            for (int nf = 0; nf < 4; nf++) {
                const uint32_t rc = (wn*32 + nf*8 + (lane & 7))*ASTRIDE + k16 + ((lane >> 3) & 1)*8;
                ldsm2(bhf[nf], smb + 2u*(2*PLANE + rc));
                ldsm2(blf[nf], smb + 2u*(3*PLANE + rc));
            }
            #pragma unroll
            for (int mf = 0; mf < 4; mf++)
                #pragma unroll
                for (int nf = 0; nf < 4; nf++) {
                    mma16816(acc[mf][nf], af[mf], bhf[nf]);
                    mma16816(acc[mf][nf], af[mf], blf[nf]);
                }
            #pragma unroll
            for (int mf = 0; mf < 4; mf++) {
                const uint32_t a = smb + 2u*(1*PLANE +
                    (wm*64 + mf*16 + (lane & 15))*ASTRIDE + k16 + (lane >> 4)*8);
                ldsm4(af[mf], a);
            }
            #pragma unroll
            for (int mf = 0; mf < 4; mf++)
                #pragma unroll
                for (int nf = 0; nf < 4; nf++)
                    mma16816(acc[mf][nf], af[mf], bhf[nf]);
        }
        __syncthreads();
    }

    const int g = mbase >> 10;
    const float* bp = (g == 0) ? bz : (g == 1) ? br : bh;
    const float* cp = (g == 0) ? cz : (g == 1) ? cr : ch;
    #pragma unroll
    for (int mf = 0; mf < 4; mf++) {
        const int row0 = wm*64 + mf*16 + (lane >> 2);
        const int jl0  = (mbase + row0) & 1023;
        const int jl8  = (mbase + row0 + 8) & 1023;
        const float bias0 = bp[jl0] + cp[jl0];
        const float bias8 = bp[jl8] + cp[jl8];
        #pragma unroll
        for (int nf = 0; nf < 4; nf++) {
            const int col0 = wn*32 + nf*8 + (lane & 3)*2;
            #pragma unroll
            for (int cc = 0; cc < 2; cc++) {
                const int n = nbase + col0 + cc;
                const int b = n >> 7;
                const int t = n & 127;
                const size_t base = ((size_t)(g*T_ + t)*B_ + b)*D_;
                g_gx[base + jl0] = acc[mf][nf][cc]     + bias0;
                g_gx[base + jl8] = acc[mf][nf][cc + 2] + bias8;
            }
        }
    }
}

// ===================== kernel 3: persistent recurrence (flags) =============
__device__ __forceinline__ void grid_barrier(int grp)
{
    __syncthreads();
    if (threadIdx.x == 0) {
        const unsigned gen = ld_acq(&g_bar_gen);
        if (atom_inc_acqrel(&g_bar_cnt[grp*32]) == GRPSZ - 1u) {
            st_rlx(&g_bar_cnt[grp*32], 0u);
            if (atom_inc_acqrel(&g_bar_root) == NGRP - 1u) {
                st_rlx(&g_bar_root, 0u);
                atom_inc_acqrel(&g_bar_gen);
            } else {
                while (ld_acq(&g_bar_gen) == gen) { }
            }
        } else {
            while (ld_acq(&g_bar_gen) == gen) { }
        }
    }
    __syncthreads();
}

#define UHSTRIDE 1032                      // bf16 elems; pad -> conflict-free LDS
#define UHP (JPC*UHSTRIDE)                 // elems per plane
#define GRU_SMEM (2*NW*512*4 + 2*UHP*2)    // 64KB partials + 66048B Uh

__global__ void __launch_bounds__(TPB, 1)
gru_kernel(float* __restrict__ out)
{
    extern __shared__ char dyn[];
    float* spar = (float*)dyn;                                   // [2][NW][512]
    __nv_bfloat16* shUh = (__nv_bfloat16*)(dyn + 2*NW*512*4);    // [2][JPC][1032]
    __shared__ float sh_z[512];
    __shared__ float sh_h[512];

    const int tid  = threadIdx.x;
    const int w    = tid >> 5;
    const int lane = tid & 31;
    const int cta  = blockIdx.x;
    const int j0   = cta * JPC;
    const int grp  = cta >> 3;
    const int gid  = lane >> 2;
    const int tig  = lane & 3;

    // ---- stage Uh (hi,lo) rows j0..j0+15 into padded SMEM
    for (int i = tid; i < 2*JPC*512; i += TPB) {     // u32 units
        const int plane = i >> 13;                   // JPC*512 = 8192
        const int rem   = i & 8191;
        const int row   = rem >> 9;
        const int k2    = rem & 511;
        const uint32_t v = *(const uint32_t*)
            &g_Ub[plane][((size_t)(2*1024 + j0 + row) << 10) + (k2 << 1)];
        *(uint32_t*)&shUh[plane*UHP + row*UHSTRIDE + (k2 << 1)] = v;
    }

    // ---- preload Uz, Ur B-fragments (hi plane only) into registers
    uint32_t buz[4][2][2], bur[4][2][2];
    #pragma unroll
    for (int nf = 0; nf < 2; nf++) {
        const int jrow = j0 + nf*8 + gid;
        #pragma unroll
        for (int kt = 0; kt < 4; kt++) {
            const int k0 = (w << 6) + (kt << 4) + (tig << 1);
            const size_t rz = ((size_t)(0*1024 + jrow) << 10) + k0;
            const size_t rr = ((size_t)(1*1024 + jrow) << 10) + k0;
            buz[kt][nf][0] = *(const uint32_t*)&g_Ub[0][rz];
            buz[kt][nf][1] = *(const uint32_t*)&g_Ub[0][rz + 8];
            bur[kt][nf][0] = *(const uint32_t*)&g_Ub[0][rr];
            bur[kt][nf][1] = *(const uint32_t*)&g_Ub[0][rr + 8];
        }
    }

    // ---- per-thread (b, j) identity + packed-store target
    const int rb  = tid >> 4;          // batch 0..31
    const int rjj = tid & 15;          // j within CTA slice
    const int rj  = j0 + rjj;
    // fragment-linear u32 index of the (k even, k odd) pair this thread's
    // value belongs to:  W = rj>>6 = cta>>2, kt = cta&3, mt = rb>>4
    const uint32_t sidx = (uint32_t)((cta >> 2)*1024
                        + (((cta & 3)*2 + (rb >> 4))*128)
                        + (((rb & 7)*4 + ((rjj >> 1) & 3))*4)
                        + ((rb >> 3) & 1) + ((rjj >> 3) << 1));
    uint32_t* hDst = &g_hA[sidx];
    uint32_t* rDst = &g_rA[sidx];
    const bool packer = !(tid & 1);    // even rjj -> low half, owns the store

    // ---- publish h0 = 0 (packed, coalesced)
    if (packer) *hDst = 0u;
    sh_h[tid] = 0.0f;
    __syncthreads();
    if (tid == 0) { fence_acqrel_gpu(); st_rel(&g_flagH[cta*32], 1u); }

    const uint32_t abase = (w << 10) + (lane << 2);
    // warp w's 4 producer flags (CTAs 4w .. 4w+3)
    const unsigned* myFH = &g_flagH[((w << 2) + (lane & 3)) * 32];
    const unsigned* myFR = &g_flagR[((w << 2) + (lane & 3)) * 32];
    const bool poller = (lane < 4);

    for (int t = 0; t < T_; t++) {
        const float gxZ = g_gx[((size_t)(0*T_ + t)*B_ + rb)*D_ + rj];
        const float gxR = g_gx[((size_t)(1*T_ + t)*B_ + rb)*D_ + rj];
        const float gxH = g_gx[((size_t)(2*T_ + t)*B_ + rb)*D_ + rj];

        // ================= phase A: z, r =================
        if (poller) { const unsigned tgt = (unsigned)(t + 1);
                      while (ld_acq(myFH) < tgt) { } }
        __syncwarp();

        #pragma unroll
        for (int mt = 0; mt < 2; mt++) {
            float cz[2][4], cr[2][4];
            #pragma unroll
            for (int nf = 0; nf < 2; nf++)
                #pragma unroll
                for (int i = 0; i < 4; i++) { cz[nf][i] = 0.0f; cr[nf][i] = 0.0f; }

            uint4 af[4];
            #pragma unroll
            for (int kt = 0; kt < 4; kt++)
                af[kt] = __ldcg((const uint4*)(g_hA + abase + ((kt*2 + mt) << 7)));
            #pragma unroll
            for (int kt = 0; kt < 4; kt++)
                #pragma unroll
                for (int nf = 0; nf < 2; nf++) {
                    mma16816(cz[nf], (const uint32_t*)&af[kt], buz[kt][nf]);
                    mma16816(cr[nf], (const uint32_t*)&af[kt], bur[kt][nf]);
                }
            const int b0 = mt*16 + gid;
            #pragma unroll
            for (int nf = 0; nf < 2; nf++) {
                const int i0 = b0*16 + nf*8 + tig*2;
                *(float2*)&spar[(0*NW + w)*512 + i0]       = make_float2(cz[nf][0], cz[nf][1]);
                *(float2*)&spar[(0*NW + w)*512 + i0 + 128] = make_float2(cz[nf][2], cz[nf][3]);
                *(float2*)&spar[(1*NW + w)*512 + i0]       = make_float2(cr[nf][0], cr[nf][1]);
                *(float2*)&spar[(1*NW + w)*512 + i0 + 128] = make_float2(cr[nf][2], cr[nf][3]);
            }
        }
        __syncthreads();
        {
            float sz = gxZ, sr = gxR;
            #pragma unroll
            for (int w2 = 0; w2 < NW; w2++) {
                sz += spar[(0*NW + w2)*512 + tid];
                sr += spar[(1*NW + w2)*512 + tid];
            }
            const float z = sigm(sz);
            const float r = sigm(sr);
            sh_z[tid] = z;
            const float rh = r * sh_h[tid];
            const uint32_t v = (uint32_t)__bfloat16_as_ushort(__float2bfloat16(rh));
            const uint32_t p = __shfl_xor_sync(0xFFFFFFFFu, v, 1);
            if (packer) *rDst = v | (p << 16);
        }
        __syncthreads();
        if (tid == 0) { fence_acqrel_gpu(); st_rel(&g_flagR[cta*32], (unsigned)(t + 1)); }

        // ================= phase B: candidate + update =================
        if (poller) { const unsigned tgt = (unsigned)(t + 1);
                      while (ld_acq(myFR) < tgt) { } }
        __syncwarp();

        #pragma unroll
        for (int mt = 0; mt < 2; mt++) {
            float ch[2][4];
            #pragma unroll
            for (int nf = 0; nf < 2; nf++)
                #pragma unroll
                for (int i = 0; i < 4; i++) ch[nf][i] = 0.0f;

            uint4 af[4];
            #pragma unroll
            for (int kt = 0; kt < 4; kt++)
                af[kt] = __ldcg((const uint4*)(g_rA + abase + ((kt*2 + mt) << 7)));
            #pragma unroll
            for (int kt = 0; kt < 4; kt++) {
                const int kcol = (w << 6) + (kt << 4) + (tig << 1);
                #pragma unroll
                for (int nf = 0; nf < 2; nf++) {
                    const __nv_bfloat16* bp = shUh + (nf*8 + gid)*UHSTRIDE + kcol;
                    uint32_t bh[2], bl[2];
                    bh[0] = *(const uint32_t*)bp;
                    bh[1] = *(const uint32_t*)(bp + 8);
                    bl[0] = *(const uint32_t*)(bp + UHP);
                    bl[1] = *(const uint32_t*)(bp + UHP + 8);
                    mma16816(ch[nf], (const uint32_t*)&af[kt], bh);
                    mma16816(ch[nf], (const uint32_t*)&af[kt], bl);
                }
            }
            const int b0 = mt*16 + gid;
            #pragma unroll
            for (int nf = 0; nf < 2; nf++) {
                const int i0 = b0*16 + nf*8 + tig*2;
                *(float2*)&spar[(0*NW + w)*512 + i0]       = make_float2(ch[nf][0], ch[nf][1]);
                *(float2*)&spar[(0*NW + w)*512 + i0 + 128] = make_float2(ch[nf][2], ch[nf][3]);
            }
        }
        __syncthreads();
        {
            float s = gxH;
            #pragma unroll
            for (int w2 = 0; w2 < NW; w2++) s += spar[(0*NW + w2)*512 + tid];
            const float hh   = sigm(s);
            const float hold = sh_h[tid];
            const float hn   = fmaf(sh_z[tid], hh - hold, hold);
            // reference reshape: flat output memory layout is (T,B,D)
            out[(size_t)t*(B_*D_) + rb*D_ + rj] = hn;
            sh_h[tid] = hn;
            const uint32_t v = (uint32_t)__bfloat16_as_ushort(__float2bfloat16(hn));
            const uint32_t p = __shfl_xor_sync(0xFFFFFFFFu, v, 1);
            if (packer) *hDst = v | (p << 16);
        }
        __syncthreads();
        if (tid == 0) { fence_acqrel_gpu(); st_rel(&g_flagH[cta*32], (unsigned)(t + 2)); }
    }

    // ---- cleanup: quiesce, then zero own flags so graph replays restart
    grid_barrier(grp);
    if (tid == 0) {
        st_rlx(&g_flagH[cta*32], 0u);
        st_rlx(&g_flagR[cta*32], 0u);
    }
}

// ===================== launch =====================
extern "C" void kernel_launch(void* const* d_in, const int* in_sizes, int n_in,
                              void* d_out, int out_size)
{
    (void)in_sizes; (void)n_in; (void)out_size;
    const float* x  = (const float*)d_in[0];
    const float* Wz = (const float*)d_in[1];
    const float* bz = (const float*)d_in[2];
    const float* Uz = (const float*)d_in[3];
    const float* cz = (const float*)d_in[4];
    const float* Wr = (const float*)d_in[5];
    const float* br = (const float*)d_in[6];
    const float* Ur = (const float*)d_in[7];
    const float* cr = (const float*)d_in[8];
    const float* Wh = (const float*)d_in[9];
    const float* bh = (const float*)d_in[10];
    const float* Uh = (const float*)d_in[11];
    const float* ch = (const float*)d_in[12];
    float* out = (float*)d_out;

    // 1) fused bf16 hi/lo split (W, U, x)
    split_all<<<2048, 256>>>(Wz, Wr, Wh, Uz, Ur, Uh, x);

    // 2) mma.sync GEMM -> g_gx (+bias)
    cudaFuncSetAttribute(gemm_kernel, cudaFuncAttributeMaxDynamicSharedMemorySize,
                         GEMM_SMEM);
    gemm_kernel<<<dim3(32, 24), GM_THREADS, GEMM_SMEM>>>(bz, cz, br, cr, bh, ch);

    // 3) persistent recurrence (p2p flags, single-plane bf16 broadcast)
    cudaFuncSetAttribute(gru_kernel, cudaFuncAttributeMaxDynamicSharedMemorySize,
                         GRU_SMEM);
    gru_kernel<<<NCTA, TPB, GRU_SMEM>>>(out);
}

// round 16
// speedup vs baseline: 2.5062x; 1.1906x over previous
#include <cuda_runtime.h>
#include <cuda_bf16.h>
#include <cstdint>

// ---------------------------------------------------------------------------
// manyToManyGRU: B=32, T=128, DIN=DOUT=1024, fp32.
//
// R15 vs R14 (1032us):
//   - Warp-granular release: phase flags are counters; each warp does its
//     packed publication stores -> __syncwarp -> lane0 red.release.gpu.add.
//     Consumers poll counter >= 16*(t+1). The CTA-wide syncthreads + fence +
//     tid0 store leave the inter-CTA critical path (spar-WAR syncthreads
//     remains, but behind the publication).
//   - gx GEMM drops the W_lo*x_hi product (keeps hi*hi + hi*lo): 48->32 mma,
//     3 staged planes. Same 2^-9-scale error as other dropped lo terms.
//   - Everything else as R14.
// ---------------------------------------------------------------------------

#define B_   32
#define T_   128
#define D_   1024
#define NCTA 64
#define JPC  16
#define TPB  512
#define NW   16
#define NGRP 8
#define GRPSZ 8

// gx layout: [(g*T + t)*B + b]*D + j
__device__ __align__(16) float g_gx[(size_t)3*T_*B_*D_];
// h / rh broadcast planes (bf16-hi only), fragment-linear
__device__ __align__(16) uint32_t g_hA[NW*1024];
__device__ __align__(16) uint32_t g_rA[NW*1024];
__device__ __align__(128) unsigned g_bar_cnt[NGRP*32];
__device__ unsigned g_bar_root = 0;
__device__ unsigned g_bar_gen  = 0;
// per-CTA monotone phase counters (128B padded); 16 warp-arrivals per phase
__device__ __align__(128) unsigned g_flagH[NCTA*32];
__device__ __align__(128) unsigned g_flagR[NCTA*32];

// bf16 split planes
__device__ __align__(16) __nv_bfloat16 g_Wb[2][(size_t)3*D_*D_];  // [(g*1024+j)*1024+k]
__device__ __align__(16) __nv_bfloat16 g_Ub[2][(size_t)3*D_*D_];  // [(g*1024+j)*1024+k]
__device__ __align__(16) __nv_bfloat16 g_xb[2][(size_t)B_*T_*D_]; // [(b*T+t)*1024+k]

__device__ __forceinline__ float sigm(float v) { return 1.0f / (1.0f + __expf(-v)); }

__device__ __forceinline__ uint32_t smem_to_u32(const void* p) {
    uint32_t a;
    asm("{ .reg .u64 t; cvta.to.shared.u64 t, %1; cvt.u32.u64 %0, t; }"
        : "=r"(a) : "l"(p));
    return a;
}
__device__ __forceinline__ void ldsm4(uint32_t* r, uint32_t a) {
    asm volatile("ldmatrix.sync.aligned.m8n8.x4.shared.b16 {%0,%1,%2,%3}, [%4];"
        : "=r"(r[0]), "=r"(r[1]), "=r"(r[2]), "=r"(r[3]) : "r"(a));
}
__device__ __forceinline__ void ldsm2(uint32_t* r, uint32_t a) {
    asm volatile("ldmatrix.sync.aligned.m8n8.x2.shared.b16 {%0,%1}, [%2];"
        : "=r"(r[0]), "=r"(r[1]) : "r"(a));
}
__device__ __forceinline__ void mma16816(float* c, const uint32_t* a, const uint32_t* b) {
    asm volatile("mma.sync.aligned.m16n8k16.row.col.f32.bf16.bf16.f32 "
        "{%0,%1,%2,%3}, {%4,%5,%6,%7}, {%8,%9}, {%0,%1,%2,%3};"
        : "+f"(c[0]), "+f"(c[1]), "+f"(c[2]), "+f"(c[3])
        : "r"(a[0]), "r"(a[1]), "r"(a[2]), "r"(a[3]), "r"(b[0]), "r"(b[1]));
}

// memory-order primitives
__device__ __forceinline__ unsigned ld_acq(const unsigned* p) {
    unsigned v;
    asm volatile("ld.acquire.gpu.global.u32 %0, [%1];" : "=r"(v) : "l"(p) : "memory");
    return v;
}
__device__ __forceinline__ unsigned atom_inc_acqrel(unsigned* p) {
    unsigned o;
    asm volatile("atom.acq_rel.gpu.global.add.u32 %0, [%1], 1;" : "=r"(o) : "l"(p) : "memory");
    return o;
}
__device__ __forceinline__ void st_rlx(unsigned* p, unsigned v) {
    asm volatile("st.relaxed.gpu.global.u32 [%0], %1;" :: "l"(p), "r"(v) : "memory");
}
__device__ __forceinline__ void red_add_rel(unsigned* p, unsigned v) {
    asm volatile("red.release.gpu.global.add.u32 [%0], %1;" :: "l"(p), "r"(v) : "memory");
}

// ===================== kernel 1: fused fp32 -> bf16 (hi,lo) split ==========
__global__ void split_all(const float* __restrict__ Wz, const float* __restrict__ Wr,
                          const float* __restrict__ Wh, const float* __restrict__ Uz,
                          const float* __restrict__ Ur, const float* __restrict__ Uh,
                          const float* __restrict__ x)
{
    const int M4  = (D_*D_) / 4;
    const int NX4 = (B_*T_*D_) / 4;
    const int tot = 6*M4 + NX4;
    for (int i = blockIdx.x*blockDim.x + threadIdx.x; i < tot;
         i += gridDim.x*blockDim.x) {
        float4 v;
        int mat, off;
        if (i < 6*M4) {
            mat = i / M4; off = i - mat*M4;
            const float* src = (mat==0)?Wz:(mat==1)?Wr:(mat==2)?Wh:
                               (mat==3)?Uz:(mat==4)?Ur:Uh;
            v = __ldg((const float4*)src + off);
        } else {
            mat = 7; off = i - 6*M4;
            v = __ldg((const float4*)x + off);
        }
        __nv_bfloat16 h0 = __float2bfloat16(v.x), h1 = __float2bfloat16(v.y);
        __nv_bfloat16 h2 = __float2bfloat16(v.z), h3 = __float2bfloat16(v.w);
        __nv_bfloat16 l0 = __float2bfloat16(v.x - __bfloat162float(h0));
        __nv_bfloat16 l1 = __float2bfloat16(v.y - __bfloat162float(h1));
        __nv_bfloat16 l2 = __float2bfloat16(v.z - __bfloat162float(h2));
        __nv_bfloat16 l3 = __float2bfloat16(v.w - __bfloat162float(h3));
        uint2 hp, lp;
        hp.x = ((uint32_t)__bfloat16_as_ushort(h1) << 16) | __bfloat16_as_ushort(h0);
        hp.y = ((uint32_t)__bfloat16_as_ushort(h3) << 16) | __bfloat16_as_ushort(h2);
        lp.x = ((uint32_t)__bfloat16_as_ushort(l1) << 16) | __bfloat16_as_ushort(l0);
        lp.y = ((uint32_t)__bfloat16_as_ushort(l3) << 16) | __bfloat16_as_ushort(l2);
        if (mat < 3) {
            *(uint2*)&g_Wb[0][(size_t)mat*D_*D_ + (size_t)off*4] = hp;
            *(uint2*)&g_Wb[1][(size_t)mat*D_*D_ + (size_t)off*4] = lp;
        } else if (mat < 6) {
            *(uint2*)&g_Ub[0][(size_t)(mat-3)*D_*D_ + (size_t)off*4] = hp;
            *(uint2*)&g_Ub[1][(size_t)(mat-3)*D_*D_ + (size_t)off*4] = lp;
        } else {
            *(uint2*)&g_xb[0][(size_t)off*4] = hp;
            *(uint2*)&g_xb[1][(size_t)off*4] = lp;
        }
    }
}

// ===================== kernel 2: mma.sync GEMM for gx ======================
// 3 staged planes (Ahi, Bhi, Blo); products: Ahi*Bhi + Ahi*Blo.
#define GM_THREADS 256
#define ASTRIDE 40
#define PLANE   (128*ASTRIDE)
#define GEMM_SMEM (3*PLANE*2)

__global__ void __launch_bounds__(GM_THREADS, 2)
gemm_kernel(const float* __restrict__ bz, const float* __restrict__ cz,
            const float* __restrict__ br, const float* __restrict__ cr,
            const float* __restrict__ bh, const float* __restrict__ ch)
{
    extern __shared__ __nv_bfloat16 sm[];
    const int tid  = threadIdx.x;
    const int w    = tid >> 5;
    const int lane = tid & 31;
    const int wm   = w >> 2;
    const int wn   = w & 3;
    const int mbase = blockIdx.y * 128;
    const int nbase = blockIdx.x * 128;
    const uint32_t smb = smem_to_u32(sm);

    float acc[4][4][4];
    #pragma unroll
    for (int mf = 0; mf < 4; mf++)
        #pragma unroll
        for (int nf = 0; nf < 4; nf++)
            #pragma unroll
            for (int i = 0; i < 4; i++) acc[mf][nf][i] = 0.0f;

    for (int kc = 0; kc < 32; kc++) {
        #pragma unroll
        for (int it = 0; it < 6; it++) {
            const int idx  = tid + it * GM_THREADS;    // < 1536
            const int part = idx >> 9;                 // 0 Ahi, 1 Bhi, 2 Blo
            const int rem  = idx & 511;
            const int row  = rem >> 2;
            const int chk  = rem & 3;
            const uint4* src = (part == 0)
                ? (const uint4*)&g_Wb[0][((size_t)(mbase + row) << 10) + kc*32 + chk*8]
                : (const uint4*)&g_xb[part - 1][((size_t)(nbase + row) << 10) + kc*32 + chk*8];
            *(uint4*)&sm[part*PLANE + row*ASTRIDE + chk*8] = __ldg(src);
        }
        __syncthreads();

        #pragma unroll
        for (int h = 0; h < 2; h++) {
            const int k16 = h * 16;
            uint32_t af[4][4], bhf[4][2], blf[4][2];
            #pragma unroll
            for (int mf = 0; mf < 4; mf++) {
                const uint32_t a = smb + 2u*(0*PLANE +
                    (wm*64 + mf*16 + (lane & 15))*ASTRIDE + k16 + (lane >> 4)*8);
                ldsm4(af[mf], a);
            }
            #pragma unroll
            for (int nf = 0; nf < 4; nf++) {
                const uint32_t rc = (wn*32 + nf*8 + (lane & 7))*ASTRIDE + k16 + ((lane >> 3) & 1)*8;
                ldsm2(bhf[nf], smb + 2u*(1*PLANE + rc));
                ldsm2(blf[nf], smb + 2u*(2*PLANE + rc));
            }
            #pragma unroll
            for (int mf = 0; mf < 4; mf++)
                #pragma unroll
                for (int nf = 0; nf < 4; nf++) {
                    mma16816(acc[mf][nf], af[mf], bhf[nf]);
                    mma16816(acc[mf][nf], af[mf], blf[nf]);
                }
        }
        __syncthreads();
    }

    const int g = mbase >> 10;
    const float* bp = (g == 0) ? bz : (g == 1) ? br : bh;
    const float* cp = (g == 0) ? cz : (g == 1) ? cr : ch;
    #pragma unroll
    for (int mf = 0; mf < 4; mf++) {
        const int row0 = wm*64 + mf*16 + (lane >> 2);
        const int jl0  = (mbase + row0) & 1023;
        const int jl8  = (mbase + row0 + 8) & 1023;
        const float bias0 = bp[jl0] + cp[jl0];
        const float bias8 = bp[jl8] + cp[jl8];
        #pragma unroll
        for (int nf = 0; nf < 4; nf++) {
            const int col0 = wn*32 + nf*8 + (lane & 3)*2;
            #pragma unroll
            for (int cc = 0; cc < 2; cc++) {
                const int n = nbase + col0 + cc;
                const int b = n >> 7;
                const int t = n & 127;
                const size_t base = ((size_t)(g*T_ + t)*B_ + b)*D_;
                g_gx[base + jl0] = acc[mf][nf][cc]     + bias0;
                g_gx[base + jl8] = acc[mf][nf][cc + 2] + bias8;
            }
        }
    }
}

// ===================== kernel 3: persistent recurrence (flags) =============
__device__ __forceinline__ void grid_barrier(int grp)
{
    __syncthreads();
    if (threadIdx.x == 0) {
        const unsigned gen = ld_acq(&g_bar_gen);
        if (atom_inc_acqrel(&g_bar_cnt[grp*32]) == GRPSZ - 1u) {
            st_rlx(&g_bar_cnt[grp*32], 0u);
            if (atom_inc_acqrel(&g_bar_root) == NGRP - 1u) {
                st_rlx(&g_bar_root, 0u);
                atom_inc_acqrel(&g_bar_gen);
            } else {
                while (ld_acq(&g_bar_gen) == gen) { }
            }
        } else {
            while (ld_acq(&g_bar_gen) == gen) { }
        }
    }
    __syncthreads();
}

#define UHSTRIDE 1032                      // bf16 elems; pad -> conflict-free LDS
#define UHP (JPC*UHSTRIDE)                 // elems per plane
#define GRU_SMEM (2*NW*512*4 + 2*UHP*2)    // 64KB partials + 66048B Uh

__global__ void __launch_bounds__(TPB, 1)
gru_kernel(float* __restrict__ out)
{
    extern __shared__ char dyn[];
    float* spar = (float*)dyn;                                   // [2][NW][512]
    __nv_bfloat16* shUh = (__nv_bfloat16*)(dyn + 2*NW*512*4);    // [2][JPC][1032]
    __shared__ float sh_z[512];
    __shared__ float sh_h[512];

    const int tid  = threadIdx.x;
    const int w    = tid >> 5;
    const int lane = tid & 31;
    const int cta  = blockIdx.x;
    const int j0   = cta * JPC;
    const int grp  = cta >> 3;
    const int gid  = lane >> 2;
    const int tig  = lane & 3;

    // ---- stage Uh (hi,lo) rows j0..j0+15 into padded SMEM
    for (int i = tid; i < 2*JPC*512; i += TPB) {     // u32 units
        const int plane = i >> 13;                   // JPC*512 = 8192
        const int rem   = i & 8191;
        const int row   = rem >> 9;
        const int k2    = rem & 511;
        const uint32_t v = *(const uint32_t*)
            &g_Ub[plane][((size_t)(2*1024 + j0 + row) << 10) + (k2 << 1)];
        *(uint32_t*)&shUh[plane*UHP + row*UHSTRIDE + (k2 << 1)] = v;
    }

    // ---- preload Uz, Ur B-fragments (hi plane only) into registers
    uint32_t buz[4][2][2], bur[4][2][2];
    #pragma unroll
    for (int nf = 0; nf < 2; nf++) {
        const int jrow = j0 + nf*8 + gid;
        #pragma unroll
        for (int kt = 0; kt < 4; kt++) {
            const int k0 = (w << 6) + (kt << 4) + (tig << 1);
            const size_t rz = ((size_t)(0*1024 + jrow) << 10) + k0;
            const size_t rr = ((size_t)(1*1024 + jrow) << 10) + k0;
            buz[kt][nf][0] = *(const uint32_t*)&g_Ub[0][rz];
            buz[kt][nf][1] = *(const uint32_t*)&g_Ub[0][rz + 8];
            bur[kt][nf][0] = *(const uint32_t*)&g_Ub[0][rr];
            bur[kt][nf][1] = *(const uint32_t*)&g_Ub[0][rr + 8];
        }
    }

    // ---- per-thread (b, j) identity + packed-store target
    const int rb  = tid >> 4;          // batch 0..31
    const int rjj = tid & 15;          // j within CTA slice
    const int rj  = j0 + rjj;
    const uint32_t sidx = (uint32_t)((cta >> 2)*1024
                        + (((cta & 3)*2 + (rb >> 4))*128)
                        + (((rb & 7)*4 + ((rjj >> 1) & 3))*4)
                        + ((rb >> 3) & 1) + ((rjj >> 3) << 1));
    uint32_t* hDst = &g_hA[sidx];
    uint32_t* rDst = &g_rA[sidx];
    const bool packer = !(tid & 1);

    // ---- publish h0 = 0 (packed; warp-granular release)
    if (packer) *hDst = 0u;
    sh_h[tid] = 0.0f;
    __syncwarp();
    if (lane == 0) red_add_rel(&g_flagH[cta*32], 1u);   // counter -> 16

    const uint32_t abase = (w << 10) + (lane << 2);
    // warp w's 4 producer counters (CTAs 4w .. 4w+3)
    const unsigned* myFH = &g_flagH[((w << 2) + (lane & 3)) * 32];
    const unsigned* myFR = &g_flagR[((w << 2) + (lane & 3)) * 32];
    const bool poller = (lane < 4);

    for (int t = 0; t < T_; t++) {
        const float gxZ = g_gx[((size_t)(0*T_ + t)*B_ + rb)*D_ + rj];
        const float gxR = g_gx[((size_t)(1*T_ + t)*B_ + rb)*D_ + rj];
        const float gxH = g_gx[((size_t)(2*T_ + t)*B_ + rb)*D_ + rj];

        // ================= phase A: z, r =================
        if (poller) { const unsigned tgt = 16u*(unsigned)(t + 1);
                      while (ld_acq(myFH) < tgt) { } }
        __syncwarp();

        #pragma unroll
        for (int mt = 0; mt < 2; mt++) {
            float cz[2][4], cr[2][4];
            #pragma unroll
            for (int nf = 0; nf < 2; nf++)
                #pragma unroll
                for (int i = 0; i < 4; i++) { cz[nf][i] = 0.0f; cr[nf][i] = 0.0f; }

            uint4 af[4];
            #pragma unroll
            for (int kt = 0; kt < 4; kt++)
                af[kt] = __ldcg((const uint4*)(g_hA + abase + ((kt*2 + mt) << 7)));
            #pragma unroll
            for (int kt = 0; kt < 4; kt++)
                #pragma unroll
                for (int nf = 0; nf < 2; nf++) {
                    mma16816(cz[nf], (const uint32_t*)&af[kt], buz[kt][nf]);
                    mma16816(cr[nf], (const uint32_t*)&af[kt], bur[kt][nf]);
                }
            const int b0 = mt*16 + gid;
            #pragma unroll
            for (int nf = 0; nf < 2; nf++) {
                const int i0 = b0*16 + nf*8 + tig*2;
                *(float2*)&spar[(0*NW + w)*512 + i0]       = make_float2(cz[nf][0], cz[nf][1]);
                *(float2*)&spar[(0*NW + w)*512 + i0 + 128] = make_float2(cz[nf][2], cz[nf][3]);
                *(float2*)&spar[(1*NW + w)*512 + i0]       = make_float2(cr[nf][0], cr[nf][1]);
                *(float2*)&spar[(1*NW + w)*512 + i0 + 128] = make_float2(cr[nf][2], cr[nf][3]);
            }
        }
        __syncthreads();
        {
            float sz = gxZ, sr = gxR;
            #pragma unroll
            for (int w2 = 0; w2 < NW; w2++) {
                sz += spar[(0*NW + w2)*512 + tid];
                sr += spar[(1*NW + w2)*512 + tid];
            }
            const float z = sigm(sz);
            const float r = sigm(sr);
            sh_z[tid] = z;
            const float rh = r * sh_h[tid];
            const uint32_t v = (uint32_t)__bfloat16_as_ushort(__float2bfloat16(rh));
            const uint32_t p = __shfl_xor_sync(0xFFFFFFFFu, v, 1);
            if (packer) *rDst = v | (p << 16);
        }
        // warp-granular publication: off the CTA-wide critical path
        __syncwarp();
        if (lane == 0) red_add_rel(&g_flagR[cta*32], 1u);
        __syncthreads();   // spar WAR before phase B writes

        // ================= phase B: candidate + update =================
        if (poller) { const unsigned tgt = 16u*(unsigned)(t + 1);
                      while (ld_acq(myFR) < tgt) { } }
        __syncwarp();

        #pragma unroll
        for (int mt = 0; mt < 2; mt++) {
            float ch[2][4];
            #pragma unroll
            for (int nf = 0; nf < 2; nf++)
                #pragma unroll
                for (int i = 0; i < 4; i++) ch[nf][i] = 0.0f;

            uint4 af[4];
            #pragma unroll
            for (int kt = 0; kt < 4; kt++)
                af[kt] = __ldcg((const uint4*)(g_rA + abase + ((kt*2 + mt) << 7)));
            #pragma unroll
            for (int kt = 0; kt < 4; kt++) {
                const int kcol = (w << 6) + (kt << 4) + (tig << 1);
                #pragma unroll
                for (int nf = 0; nf < 2; nf++) {
                    const __nv_bfloat16* bp = shUh + (nf*8 + gid)*UHSTRIDE + kcol;
                    uint32_t bh[2], bl[2];
                    bh[0] = *(const uint32_t*)bp;
                    bh[1] = *(const uint32_t*)(bp + 8);
                    bl[0] = *(const uint32_t*)(bp + UHP);
                    bl[1] = *(const uint32_t*)(bp + UHP + 8);
                    mma16816(ch[nf], (const uint32_t*)&af[kt], bh);
                    mma16816(ch[nf], (const uint32_t*)&af[kt], bl);
                }
            }
            const int b0 = mt*16 + gid;
            #pragma unroll
            for (int nf = 0; nf < 2; nf++) {
                const int i0 = b0*16 + nf*8 + tig*2;
                *(float2*)&spar[(0*NW + w)*512 + i0]       = make_float2(ch[nf][0], ch[nf][1]);
                *(float2*)&spar[(0*NW + w)*512 + i0 + 128] = make_float2(ch[nf][2], ch[nf][3]);
            }
        }
        __syncthreads();
        {
            float s = gxH;
            #pragma unroll
            for (int w2 = 0; w2 < NW; w2++) s += spar[(0*NW + w2)*512 + tid];
            const float hh   = sigm(s);
            const float hold = sh_h[tid];
            const float hn   = fmaf(sh_z[tid], hh - hold, hold);
            // reference reshape: flat output memory layout is (T,B,D)
            out[(size_t)t*(B_*D_) + rb*D_ + rj] = hn;
            sh_h[tid] = hn;
            const uint32_t v = (uint32_t)__bfloat16_as_ushort(__float2bfloat16(hn));
            const uint32_t p = __shfl_xor_sync(0xFFFFFFFFu, v, 1);
            if (packer) *hDst = v | (p << 16);
        }
        __syncwarp();
        if (lane == 0) red_add_rel(&g_flagH[cta*32], 1u);
        __syncthreads();   // spar WAR before next phase A writes
    }

    // ---- cleanup: quiesce, then zero own counters so graph replays restart
    grid_barrier(grp);
    if (tid == 0) {
        st_rlx(&g_flagH[cta*32], 0u);
        st_rlx(&g_flagR[cta*32], 0u);
    }
}

// ===================== launch =====================
extern "C" void kernel_launch(void* const* d_in, const int* in_sizes, int n_in,
                              void* d_out, int out_size)
{
    (void)in_sizes; (void)n_in; (void)out_size;
    const float* x  = (const float*)d_in[0];
    const float* Wz = (const float*)d_in[1];
    const float* bz = (const float*)d_in[2];
    const float* Uz = (const float*)d_in[3];
    const float* cz = (const float*)d_in[4];
    const float* Wr = (const float*)d_in[5];
    const float* br = (const float*)d_in[6];
    const float* Ur = (const float*)d_in[7];
    const float* cr = (const float*)d_in[8];
    const float* Wh = (const float*)d_in[9];
    const float* bh = (const float*)d_in[10];
    const float* Uh = (const float*)d_in[11];
    const float* ch = (const float*)d_in[12];
    float* out = (float*)d_out;

    // 1) fused bf16 hi/lo split (W, U, x)
    split_all<<<2048, 256>>>(Wz, Wr, Wh, Uz, Ur, Uh, x);

    // 2) mma.sync GEMM -> g_gx (+bias)
    cudaFuncSetAttribute(gemm_kernel, cudaFuncAttributeMaxDynamicSharedMemorySize,
                         GEMM_SMEM);
    gemm_kernel<<<dim3(32, 24), GM_THREADS, GEMM_SMEM>>>(bz, cz, br, cr, bh, ch);

    // 3) persistent recurrence (warp-granular release counters)
    cudaFuncSetAttribute(gru_kernel, cudaFuncAttributeMaxDynamicSharedMemorySize,
                         GRU_SMEM);
    gru_kernel<<<NCTA, TPB, GRU_SMEM>>>(out);
}